// round 12
// baseline (speedup 1.0000x reference)
#include <cuda_runtime.h>
#include <cuda_fp16.h>
#include <cstdint>

typedef uint32_t u32;

static constexpr int NB = 32, NN = 128, DD = 64;
static constexpr int NCTA = 296;           // 148 SMs x 2 resident CTAs -> single wave
static constexpr int NTILES = NB * NN;     // 4096

// Precomputed A-transpose fp16 image: At[j][k] = A[b][k][j],
// 128 rows, row stride 136 fp16 (272B), 128 valid k + pad.
__device__ __align__(16) unsigned char g_Ah[32][34816];

// ---------------- helpers ----------------
__device__ __forceinline__ u32 smem_u32(const void* p) {
    u32 a;
    asm("{ .reg .u64 t; cvta.to.shared.u64 t, %1; cvt.u32.u64 %0, t; }" : "=r"(a) : "l"(p));
    return a;
}
__device__ __forceinline__ u32 pack_h16(float lo, float hi) {
    u32 r;
    asm("cvt.rn.f16x2.f32 %0, %1, %2;" : "=r"(r) : "f"(hi), "f"(lo));
    return r;
}
__device__ __forceinline__ void sts32(u32 a, u32 v) {
    asm volatile("st.shared.b32 [%0], %1;" :: "r"(a), "r"(v) : "memory");
}
__device__ __forceinline__ void sts64(u32 a, u32 x, u32 y) {
    asm volatile("st.shared.v2.b32 [%0], {%1,%2};" :: "r"(a), "r"(x), "r"(y) : "memory");
}
__device__ __forceinline__ void sts128(u32 a, u32 x, u32 y, u32 z, u32 w) {
    asm volatile("st.shared.v4.b32 [%0], {%1,%2,%3,%4};" :: "r"(a), "r"(x), "r"(y), "r"(z), "r"(w) : "memory");
}
__device__ __forceinline__ void lds64f(float& x, float& y, u32 a) {
    asm volatile("ld.shared.v2.f32 {%0,%1}, [%2];" : "=f"(x), "=f"(y) : "r"(a));
}
__device__ __forceinline__ void ldsm4(u32* f, u32 a) {
    asm volatile("ldmatrix.sync.aligned.m8n8.x4.shared.b16 {%0,%1,%2,%3}, [%4];"
                 : "=r"(f[0]), "=r"(f[1]), "=r"(f[2]), "=r"(f[3]) : "r"(a));
}
__device__ __forceinline__ void ldsm4t(u32* f, u32 a) {
    asm volatile("ldmatrix.sync.aligned.m8n8.x4.trans.shared.b16 {%0,%1,%2,%3}, [%4];"
                 : "=r"(f[0]), "=r"(f[1]), "=r"(f[2]), "=r"(f[3]) : "r"(a));
}
__device__ __forceinline__ void mma_f16(float* c, const u32* a, const u32* b) {
    asm volatile(
        "mma.sync.aligned.m16n8k16.row.col.f32.f16.f16.f32 "
        "{%0,%1,%2,%3}, {%4,%5,%6,%7}, {%8,%9}, {%0,%1,%2,%3};"
        : "+f"(c[0]), "+f"(c[1]), "+f"(c[2]), "+f"(c[3])
        : "r"(a[0]), "r"(a[1]), "r"(a[2]), "r"(a[3]), "r"(b[0]), "r"(b[1]));
}

// ---------------- smem layout (R11 + second X buffer) ----------------
static constexpr u32 RS64  = 144;   // 64-wide fp16 tile row stride (bytes)
static constexpr u32 RS128 = 272;   // 128-wide tile row stride

static constexpr u32 OFF_X0 = 0;        // 18432
static constexpr u32 OFF_X1 = 18432;    // 18432
static constexpr u32 OFF_W1 = 36864;    // 9216
static constexpr u32 OFF_W2 = 46080;    // 9216
static constexpr u32 OFF_AT = 55296;    // 34816
static constexpr u32 OFF_H2 = 90112;    // 18432
static constexpr u32 OFF_B1 = 108544;   // 256
static constexpr u32 OFF_B2 = 108800;   // 256
static constexpr u32 SMEM_BYTES = 109056; // 2 x 109056 = 218112 <= 227KB/SM -> 2 CTAs

// =============== prep: A[b][k][j] -> At fp16 image ===============
__global__ void prep_At(const float* __restrict__ A)
{
    __shared__ float tile[32][33];
    const int b = blockIdx.z, k0 = blockIdx.x * 32, j0 = blockIdx.y * 32;
    const int tx = threadIdx.x & 31, ty = threadIdx.x >> 5;   // ty: 0..7

    const float* Ab = A + ((size_t)b * NN + k0) * NN + j0;
    #pragma unroll
    for (int s = 0; s < 4; ++s)
        tile[ty + 8 * s][tx] = Ab[(ty + 8 * s) * NN + tx];
    __syncthreads();

    const int j  = threadIdx.x >> 3;   // 0..31
    const int kq = threadIdx.x & 7;    // 4 k values each
    float v[4];
    #pragma unroll
    for (int s = 0; s < 4; ++s) v[s] = tile[kq * 4 + s][j];

    uint2 h = make_uint2(pack_h16(v[0], v[1]), pack_h16(v[2], v[3]));
    size_t off = (size_t)(j0 + j) * RS128 + (size_t)(k0 + kq * 4) * 2;
    *reinterpret_cast<uint2*>(&g_Ah[b][off]) = h;
}

// X tile stage: fp32 global -> fp16 smem (coalesced float4 loads)
__device__ __forceinline__ void stage_X(const float* __restrict__ X, int t,
                                        u32 dst, int tid)
{
    const float4* gX4 = (const float4*)(X + (size_t)t * (NN * DD));  // 2048 float4
    #pragma unroll
    for (int it = 0; it < 8; ++it) {
        int q = tid + it * 256;
        float4 v = gX4[q];
        int k = q >> 4, dq = (q & 15) * 4;
        sts64(dst + (u32)k * RS64 + (u32)dq * 2,
              pack_h16(v.x, v.y), pack_h16(v.z, v.w));
    }
}

// =============== main fused persistent kernel ===============
__global__ __launch_bounds__(256, 2)
void crosssubg_mma_kernel(const float* __restrict__ X,
                          const float* __restrict__ W1,
                          const float* __restrict__ b1,
                          const float* __restrict__ W2,
                          const float* __restrict__ b2,
                          float* __restrict__ out)
{
    extern __shared__ __align__(256) unsigned char smraw[];
    const u32 sb = smem_u32(smraw);

    const int cta  = blockIdx.x;
    const int tid  = (int)threadIdx.x;
    const int wid  = tid >> 5;
    const int lane = tid & 31;
    const int row0 = wid * 16;              // G1/G2 m-rows
    const int wm   = wid >> 1, wn = wid & 1;
    const int j0   = wm * 32, d0 = wn * 32; // G3 warp tile origin
    const int fr   = lane >> 2, fc = lane & 3;

    const int t_begin = (int)(((long long)cta * NTILES) / NCTA);
    const int t_end   = (int)(((long long)(cta + 1) * NTILES) / NCTA);

    // ---- one-time staging: W1, W2, biases ----
    {
        const float4* gW1 = (const float4*)W1;   // 1024 each
        const float4* gW2 = (const float4*)W2;
        #pragma unroll
        for (int it = 0; it < 8; ++it) {
            int t = tid + it * 256;              // 0..2047
            int sel = t >> 10;
            int r = t & 1023;
            float4 v = sel ? gW2[r] : gW1[r];
            int d = r >> 4, e0 = (r & 15) * 4;
            sts64(sb + (sel ? OFF_W2 : OFF_W1) + (u32)d * RS64 + (u32)e0 * 2,
                  pack_h16(v.x, v.y), pack_h16(v.z, v.w));
        }
        if (tid < 64)       sts32(sb + OFF_B1 + (u32)tid * 4, __float_as_uint(__ldg(&b1[tid])));
        else if (tid < 128) sts32(sb + OFF_B2 + (u32)(tid - 64) * 4, __float_as_uint(__ldg(&b2[tid - 64])));
    }

    // precomputed addresses (X fragment address without buffer base)
    const u32 aoffXr = ((u32)row0 + (u32)(lane & 15)) * RS64 + (u32)(lane >> 4) * 16;
    const u32 boffW  = (u32)(lane & 15) * RS64 + (u32)(lane >> 4) * 16;
    const u32 aoffA  = sb + OFF_AT + ((u32)j0 + (u32)(lane & 15)) * RS128 + (u32)(lane >> 4) * 16;
    const u32 boffH  = sb + OFF_H2 + (u32)(lane & 15) * RS64 + (u32)d0 * 2 + (u32)(lane >> 4) * 16;

    int cur_b = -1;

    // prologue: stage first X tile
    stage_X(X, t_begin, sb + ((t_begin & 1) ? OFF_X1 : OFF_X0), tid);

    for (int t = t_begin; t < t_end; ++t) {
        const int b = t >> 7;   // tile / 128
        const u32 xbuf = sb + ((t & 1) ? OFF_X1 : OFF_X0);

        // ---- At (re)stage on batch change: <=2 per CTA ----
        if (b != cur_b) {
            __syncthreads();       // no warp still reading At in G3(t-1)
            cur_b = b;
            const uint4* gA = (const uint4*)&g_Ah[b][0];   // 2176 uint4
            #pragma unroll
            for (int it = 0; it < 9; ++it) {
                int q = tid + it * 256;
                if (q < 2176) {
                    uint4 v = gA[q];
                    sts128(sb + OFF_AT + (u32)q * 16, v.x, v.y, v.z, v.w);
                }
            }
        }

        __syncthreads();   // bar1: X(t) (+At) visible; all warps past G3(t-1)

        // ---- GEMM1: acc1 = X W1  (M=128 N=64 K=64) ----
        float acc1[8][4];
        #pragma unroll
        for (int n = 0; n < 8; ++n)
            #pragma unroll
            for (int q = 0; q < 4; ++q) acc1[n][q] = 0.0f;
        #pragma unroll
        for (int ks = 0; ks < 4; ++ks) {
            u32 fa[4];
            ldsm4(fa, xbuf + aoffXr + (u32)ks * 32);
            const u32 bb = sb + OFF_W1 + (u32)ks * 16 * RS64 + boffW;
            #pragma unroll
            for (int np = 0; np < 4; ++np) {
                u32 fb[4];
                ldsm4t(fb, bb + (u32)np * 32);
                mma_f16(acc1[2 * np],     fa, fb);
                mma_f16(acc1[2 * np + 1], fa, fb + 2);
            }
        }

        // ---- GEMM2: acc2 = relu(acc1 + b1) W2, A-fragments built in registers ----
        float acc2[8][4];
        #pragma unroll
        for (int n = 0; n < 8; ++n)
            #pragma unroll
            for (int q = 0; q < 4; ++q) acc2[n][q] = 0.0f;
        #pragma unroll
        for (int ks = 0; ks < 4; ++ks) {
            float bz0, bz1, bz2, bz3;
            lds64f(bz0, bz1, sb + OFF_B1 + (u32)(16 * ks + 2 * fc) * 4);
            lds64f(bz2, bz3, sb + OFF_B1 + (u32)(16 * ks + 8 + 2 * fc) * 4);
            u32 fa[4];
            fa[0] = pack_h16(fmaxf(acc1[2 * ks][0] + bz0, 0.f), fmaxf(acc1[2 * ks][1] + bz1, 0.f));
            fa[1] = pack_h16(fmaxf(acc1[2 * ks][2] + bz0, 0.f), fmaxf(acc1[2 * ks][3] + bz1, 0.f));
            fa[2] = pack_h16(fmaxf(acc1[2 * ks + 1][0] + bz2, 0.f), fmaxf(acc1[2 * ks + 1][1] + bz3, 0.f));
            fa[3] = pack_h16(fmaxf(acc1[2 * ks + 1][2] + bz2, 0.f), fmaxf(acc1[2 * ks + 1][3] + bz3, 0.f));
            const u32 bb = sb + OFF_W2 + (u32)ks * 16 * RS64 + boffW;
            #pragma unroll
            for (int np = 0; np < 4; ++np) {
                u32 fb[4];
                ldsm4t(fb, bb + (u32)np * 32);
                mma_f16(acc2[2 * np],     fa, fb);
                mma_f16(acc2[2 * np + 1], fa, fb + 2);
            }
        }

        // ---- h2 = relu(acc2 + b2) -> smem fp16 (separate region) ----
        {
            const int r  = row0 + fr;
            const int cb = 2 * fc;
            #pragma unroll
            for (int n0 = 0; n0 < 8; ++n0) {
                const int col = n0 * 8 + cb;
                float bz0, bz1;
                lds64f(bz0, bz1, sb + OFF_B2 + (u32)col * 4);
                float v0 = fmaxf(acc2[n0][0] + bz0, 0.f);
                float v1 = fmaxf(acc2[n0][1] + bz1, 0.f);
                float v2 = fmaxf(acc2[n0][2] + bz0, 0.f);
                float v3 = fmaxf(acc2[n0][3] + bz1, 0.f);
                const u32 a0 = sb + OFF_H2 + (u32)r * RS64 + (u32)col * 2;
                sts32(a0,             pack_h16(v0, v1));
                sts32(a0 + 8u * RS64, pack_h16(v2, v3));
            }
        }
        __syncthreads();   // bar2: h2 visible

        // ---- prefetch X(t+1) into the other buffer; DRAM latency hides under G3 ----
        if (t + 1 < t_end)
            stage_X(X, t + 1, sb + (((t + 1) & 1) ? OFF_X1 : OFF_X0), tid);

        // ---- GEMM3: out[j][d] = sum_k At[j][k] h2[k][d]  (warp tile 32x32) ----
        float acc3[8][4];
        #pragma unroll
        for (int n = 0; n < 8; ++n)
            #pragma unroll
            for (int q = 0; q < 4; ++q) acc3[n][q] = 0.0f;
        #pragma unroll
        for (int ks = 0; ks < 8; ++ks) {
            u32 fa0[4], fa1[4], fb0[4], fb1[4];
            ldsm4(fa0, aoffA + (u32)ks * 32);
            ldsm4(fa1, aoffA + 16u * RS128 + (u32)ks * 32);
            const u32 bb = boffH + (u32)ks * 16 * RS64;
            ldsm4t(fb0, bb);
            ldsm4t(fb1, bb + 32);
            mma_f16(acc3[0], fa0, fb0); mma_f16(acc3[1], fa0, fb0 + 2);
            mma_f16(acc3[2], fa0, fb1); mma_f16(acc3[3], fa0, fb1 + 2);
            mma_f16(acc3[4], fa1, fb0); mma_f16(acc3[5], fa1, fb0 + 2);
            mma_f16(acc3[6], fa1, fb1); mma_f16(acc3[7], fa1, fb1 + 2);
        }

        // ---- store to global ----
        {
            float* gO = out + (size_t)t * (NN * DD);
            const int cb = 2 * fc;
            #pragma unroll
            for (int mb = 0; mb < 2; ++mb) {
                const int j = j0 + 16 * mb + fr;
                #pragma unroll
                for (int nb = 0; nb < 4; ++nb) {
                    const float* a = acc3[mb * 4 + nb];
                    const int col = d0 + 8 * nb + cb;
                    *(float2*)(gO + (size_t)j * DD + col)       = make_float2(a[0], a[1]);
                    *(float2*)(gO + (size_t)(j + 8) * DD + col) = make_float2(a[2], a[3]);
                }
            }
        }
    }
}

extern "C" void kernel_launch(void* const* d_in, const int* in_sizes, int n_in,
                              void* d_out, int out_size)
{
    const float *X = nullptr, *A = nullptr, *W1 = nullptr, *b1 = nullptr,
                *W2 = nullptr, *b2 = nullptr;
    for (int idx = 0; idx < n_in; ++idx) {
        const float* p = (const float*)d_in[idx];
        int s = in_sizes[idx];
        if      (s == NB * NN * NN * DD) X = p;
        else if (s == NB * NN * NN)      A = p;
        else if (s == DD * DD)           { if (!W1) W1 = p; else W2 = p; }
        else if (s == DD)                { if (!b1) b1 = p; else b2 = p; }
    }

    prep_At<<<dim3(4, 4, 32), 256>>>(A);

    cudaFuncSetAttribute(crosssubg_mma_kernel,
                         cudaFuncAttributeMaxDynamicSharedMemorySize, SMEM_BYTES);
    crosssubg_mma_kernel<<<NCTA, 256, SMEM_BYTES>>>(X, W1, b1, W2, b2, (float*)d_out);
}

// round 13
// speedup vs baseline: 1.1433x; 1.1433x over previous
#include <cuda_runtime.h>
#include <cuda_fp16.h>
#include <cstdint>

typedef uint32_t u32;

static constexpr int NB = 32, NN = 128, DD = 64;
static constexpr int NCTA = 296;           // 148 SMs x 2 resident CTAs -> single wave
static constexpr int NTILES = NB * NN;     // 4096

// Precomputed A-transpose fp16 image: At[j][k] = A[b][k][j],
// 128 rows, row stride 136 fp16 (272B), 128 valid k + pad.
__device__ __align__(16) unsigned char g_Ah[32][34816];

// ---------------- helpers ----------------
__device__ __forceinline__ u32 smem_u32(const void* p) {
    u32 a;
    asm("{ .reg .u64 t; cvta.to.shared.u64 t, %1; cvt.u32.u64 %0, t; }" : "=r"(a) : "l"(p));
    return a;
}
__device__ __forceinline__ u32 pack_h16(float lo, float hi) {
    u32 r;
    asm("cvt.rn.f16x2.f32 %0, %1, %2;" : "=r"(r) : "f"(hi), "f"(lo));
    return r;
}
__device__ __forceinline__ void sts32(u32 a, u32 v) {
    asm volatile("st.shared.b32 [%0], %1;" :: "r"(a), "r"(v) : "memory");
}
__device__ __forceinline__ void sts64(u32 a, u32 x, u32 y) {
    asm volatile("st.shared.v2.b32 [%0], {%1,%2};" :: "r"(a), "r"(x), "r"(y) : "memory");
}
__device__ __forceinline__ void sts128(u32 a, u32 x, u32 y, u32 z, u32 w) {
    asm volatile("st.shared.v4.b32 [%0], {%1,%2,%3,%4};" :: "r"(a), "r"(x), "r"(y), "r"(z), "r"(w) : "memory");
}
__device__ __forceinline__ void lds64f(float& x, float& y, u32 a) {
    asm volatile("ld.shared.v2.f32 {%0,%1}, [%2];" : "=f"(x), "=f"(y) : "r"(a));
}
__device__ __forceinline__ void ldsm4(u32* f, u32 a) {
    asm volatile("ldmatrix.sync.aligned.m8n8.x4.shared.b16 {%0,%1,%2,%3}, [%4];"
                 : "=r"(f[0]), "=r"(f[1]), "=r"(f[2]), "=r"(f[3]) : "r"(a));
}
__device__ __forceinline__ void ldsm4t(u32* f, u32 a) {
    asm volatile("ldmatrix.sync.aligned.m8n8.x4.trans.shared.b16 {%0,%1,%2,%3}, [%4];"
                 : "=r"(f[0]), "=r"(f[1]), "=r"(f[2]), "=r"(f[3]) : "r"(a));
}
__device__ __forceinline__ void mma_f16(float* c, const u32* a, const u32* b) {
    asm volatile(
        "mma.sync.aligned.m16n8k16.row.col.f32.f16.f16.f32 "
        "{%0,%1,%2,%3}, {%4,%5,%6,%7}, {%8,%9}, {%0,%1,%2,%3};"
        : "+f"(c[0]), "+f"(c[1]), "+f"(c[2]), "+f"(c[3])
        : "r"(a[0]), "r"(a[1]), "r"(a[2]), "r"(a[3]), "r"(b[0]), "r"(b[1]));
}

// ---------------- smem layout (identical to the 86.0us R11 kernel) ----------------
static constexpr u32 RS64  = 144;   // 64-wide fp16 tile row stride (bytes)
static constexpr u32 RS128 = 272;   // 128-wide tile row stride

static constexpr u32 OFF_X  = 0;        // 18432
static constexpr u32 OFF_W1 = 18432;    // 9216
static constexpr u32 OFF_W2 = 27648;    // 9216
static constexpr u32 OFF_AT = 36864;    // 34816
static constexpr u32 OFF_H2 = 71680;    // 18432
static constexpr u32 OFF_B1 = 90112;    // 256
static constexpr u32 OFF_B2 = 90368;    // 256
static constexpr u32 SMEM_BYTES = 90624; // -> 2 CTAs/SM

// =============== prep: A[b][k][j] -> At fp16 image ===============
__global__ void prep_At(const float* __restrict__ A)
{
    __shared__ float tile[32][33];
    const int b = blockIdx.z, k0 = blockIdx.x * 32, j0 = blockIdx.y * 32;
    const int tx = threadIdx.x & 31, ty = threadIdx.x >> 5;   // ty: 0..7

    const float* Ab = A + ((size_t)b * NN + k0) * NN + j0;
    #pragma unroll
    for (int s = 0; s < 4; ++s)
        tile[ty + 8 * s][tx] = Ab[(ty + 8 * s) * NN + tx];
    __syncthreads();

    const int j  = threadIdx.x >> 3;   // 0..31
    const int kq = threadIdx.x & 7;    // 4 k values each
    float v[4];
    #pragma unroll
    for (int s = 0; s < 4; ++s) v[s] = tile[kq * 4 + s][j];

    uint2 h = make_uint2(pack_h16(v[0], v[1]), pack_h16(v[2], v[3]));
    size_t off = (size_t)(j0 + j) * RS128 + (size_t)(k0 + kq * 4) * 2;
    *reinterpret_cast<uint2*>(&g_Ah[b][off]) = h;
}

// =============== main fused persistent kernel ===============
__global__ __launch_bounds__(256, 2)
void crosssubg_mma_kernel(const float* __restrict__ X,
                          const float* __restrict__ W1,
                          const float* __restrict__ b1,
                          const float* __restrict__ W2,
                          const float* __restrict__ b2,
                          float* __restrict__ out)
{
    extern __shared__ __align__(256) unsigned char smraw[];
    const u32 sb = smem_u32(smraw);

    const int cta  = blockIdx.x;
    const int tid  = (int)threadIdx.x;
    const int wid  = tid >> 5;
    const int lane = tid & 31;
    const int row0 = wid * 16;              // G1/G2 m-rows
    const int wm   = wid >> 1, wn = wid & 1;
    const int j0   = wm * 32, d0 = wn * 32; // G3 warp tile origin
    const int fr   = lane >> 2, fc = lane & 3;

    const int t_begin = (int)(((long long)cta * NTILES) / NCTA);
    const int t_end   = (int)(((long long)(cta + 1) * NTILES) / NCTA);

    // ---- one-time staging: W1, W2, biases ----
    {
        const float4* gW1 = (const float4*)W1;   // 1024 each
        const float4* gW2 = (const float4*)W2;
        #pragma unroll
        for (int it = 0; it < 8; ++it) {
            int t = tid + it * 256;              // 0..2047
            int sel = t >> 10;
            int r = t & 1023;
            float4 v = sel ? gW2[r] : gW1[r];
            int d = r >> 4, e0 = (r & 15) * 4;
            sts64(sb + (sel ? OFF_W2 : OFF_W1) + (u32)d * RS64 + (u32)e0 * 2,
                  pack_h16(v.x, v.y), pack_h16(v.z, v.w));
        }
        if (tid < 64)       sts32(sb + OFF_B1 + (u32)tid * 4, __float_as_uint(__ldg(&b1[tid])));
        else if (tid < 128) sts32(sb + OFF_B2 + (u32)(tid - 64) * 4, __float_as_uint(__ldg(&b2[tid - 64])));
    }

    // precomputed addresses
    const u32 aoffX = sb + OFF_X + ((u32)row0 + (u32)(lane & 15)) * RS64 + (u32)(lane >> 4) * 16;
    const u32 boffW = (u32)(lane & 15) * RS64 + (u32)(lane >> 4) * 16;
    const u32 aoffA = sb + OFF_AT + ((u32)j0 + (u32)(lane & 15)) * RS128 + (u32)(lane >> 4) * 16;
    const u32 boffH = sb + OFF_H2 + (u32)(lane & 15) * RS64 + (u32)d0 * 2 + (u32)(lane >> 4) * 16;

    int cur_b = -1;

    for (int t = t_begin; t < t_end; ++t) {
        const int b = t >> 7;   // tile / 128

        // ---- At (re)stage on batch change: <=2 per CTA ----
        if (b != cur_b) {
            __syncthreads();       // no warp still reading At in G3(t-1)
            cur_b = b;
            const uint4* gA = (const uint4*)&g_Ah[b][0];   // 2176 uint4
            #pragma unroll
            for (int it = 0; it < 9; ++it) {
                int q = tid + it * 256;
                if (q < 2176) {
                    uint4 v = gA[q];
                    sts128(sb + OFF_AT + (u32)q * 16, v.x, v.y, v.z, v.w);
                }
            }
        }

        // ---- stage X (fp16, coalesced float4); X region not read by G3(t-1) ----
        {
            const float4* gX4 = (const float4*)(X + (size_t)t * (NN * DD));  // 2048 float4
            #pragma unroll
            for (int it = 0; it < 8; ++it) {
                int q = tid + it * 256;
                float4 v = gX4[q];
                int k = q >> 4, dq = (q & 15) * 4;
                sts64(sb + OFF_X + (u32)k * RS64 + (u32)dq * 2,
                      pack_h16(v.x, v.y), pack_h16(v.z, v.w));
            }
        }
        __syncthreads();   // bar1: X (+At) visible; all warps past G3(t-1)

        // ---- GEMM1: acc1 = X W1  (batched loads: 1 latency exposure per ks) ----
        float acc1[8][4];
        #pragma unroll
        for (int n = 0; n < 8; ++n)
            #pragma unroll
            for (int q = 0; q < 4; ++q) acc1[n][q] = 0.0f;
        #pragma unroll
        for (int ks = 0; ks < 4; ++ks) {
            const u32 bb = sb + OFF_W1 + (u32)ks * 16 * RS64 + boffW;
            u32 fa[4], fb0[4], fb1[4], fb2[4], fb3[4];
            ldsm4 (fa,  aoffX + (u32)ks * 32);
            ldsm4t(fb0, bb);
            ldsm4t(fb1, bb + 32);
            ldsm4t(fb2, bb + 64);
            ldsm4t(fb3, bb + 96);
            mma_f16(acc1[0], fa, fb0); mma_f16(acc1[1], fa, fb0 + 2);
            mma_f16(acc1[2], fa, fb1); mma_f16(acc1[3], fa, fb1 + 2);
            mma_f16(acc1[4], fa, fb2); mma_f16(acc1[5], fa, fb2 + 2);
            mma_f16(acc1[6], fa, fb3); mma_f16(acc1[7], fa, fb3 + 2);
        }

        // ---- GEMM2: acc2 = relu(acc1 + b1) W2 (A-frags in regs; batched B loads) ----
        float acc2[8][4];
        #pragma unroll
        for (int n = 0; n < 8; ++n)
            #pragma unroll
            for (int q = 0; q < 4; ++q) acc2[n][q] = 0.0f;
        #pragma unroll
        for (int ks = 0; ks < 4; ++ks) {
            const u32 bb = sb + OFF_W2 + (u32)ks * 16 * RS64 + boffW;
            u32 fb0[4], fb1[4], fb2[4], fb3[4];
            ldsm4t(fb0, bb);
            ldsm4t(fb1, bb + 32);
            ldsm4t(fb2, bb + 64);
            ldsm4t(fb3, bb + 96);
            float bz0, bz1, bz2, bz3;
            lds64f(bz0, bz1, sb + OFF_B1 + (u32)(16 * ks + 2 * fc) * 4);
            lds64f(bz2, bz3, sb + OFF_B1 + (u32)(16 * ks + 8 + 2 * fc) * 4);
            u32 fa[4];
            fa[0] = pack_h16(fmaxf(acc1[2 * ks][0] + bz0, 0.f), fmaxf(acc1[2 * ks][1] + bz1, 0.f));
            fa[1] = pack_h16(fmaxf(acc1[2 * ks][2] + bz0, 0.f), fmaxf(acc1[2 * ks][3] + bz1, 0.f));
            fa[2] = pack_h16(fmaxf(acc1[2 * ks + 1][0] + bz2, 0.f), fmaxf(acc1[2 * ks + 1][1] + bz3, 0.f));
            fa[3] = pack_h16(fmaxf(acc1[2 * ks + 1][2] + bz2, 0.f), fmaxf(acc1[2 * ks + 1][3] + bz3, 0.f));
            mma_f16(acc2[0], fa, fb0); mma_f16(acc2[1], fa, fb0 + 2);
            mma_f16(acc2[2], fa, fb1); mma_f16(acc2[3], fa, fb1 + 2);
            mma_f16(acc2[4], fa, fb2); mma_f16(acc2[5], fa, fb2 + 2);
            mma_f16(acc2[6], fa, fb3); mma_f16(acc2[7], fa, fb3 + 2);
        }

        // ---- h2 = relu(acc2 + b2) -> smem fp16 (separate region) ----
        {
            const int r  = row0 + fr;
            const int cb = 2 * fc;
            #pragma unroll
            for (int n0 = 0; n0 < 8; ++n0) {
                const int col = n0 * 8 + cb;
                float bz0, bz1;
                lds64f(bz0, bz1, sb + OFF_B2 + (u32)col * 4);
                float v0 = fmaxf(acc2[n0][0] + bz0, 0.f);
                float v1 = fmaxf(acc2[n0][1] + bz1, 0.f);
                float v2 = fmaxf(acc2[n0][2] + bz0, 0.f);
                float v3 = fmaxf(acc2[n0][3] + bz1, 0.f);
                const u32 a0 = sb + OFF_H2 + (u32)r * RS64 + (u32)col * 2;
                sts32(a0,             pack_h16(v0, v1));
                sts32(a0 + 8u * RS64, pack_h16(v2, v3));
            }
        }
        __syncthreads();   // bar2: h2 visible

        // ---- GEMM3 (software-pipelined: fragment loads one ks ahead) ----
        float acc3[8][4];
        #pragma unroll
        for (int n = 0; n < 8; ++n)
            #pragma unroll
            for (int q = 0; q < 4; ++q) acc3[n][q] = 0.0f;

        u32 pa0[2][4], pa1[2][4], pb0[2][4], pb1[2][4];
        // prologue: loads for ks=0
        ldsm4 (pa0[0], aoffA);
        ldsm4 (pa1[0], aoffA + 16u * RS128);
        ldsm4t(pb0[0], boffH);
        ldsm4t(pb1[0], boffH + 32);
        #pragma unroll
        for (int ks = 0; ks < 8; ++ks) {
            const int cur = ks & 1, nxt = cur ^ 1;
            if (ks < 7) {
                const u32 an = aoffA + (u32)(ks + 1) * 32;
                const u32 bn = boffH + (u32)(ks + 1) * 16 * RS64;
                ldsm4 (pa0[nxt], an);
                ldsm4 (pa1[nxt], an + 16u * RS128);
                ldsm4t(pb0[nxt], bn);
                ldsm4t(pb1[nxt], bn + 32);
            }
            mma_f16(acc3[0], pa0[cur], pb0[cur]); mma_f16(acc3[1], pa0[cur], pb0[cur] + 2);
            mma_f16(acc3[2], pa0[cur], pb1[cur]); mma_f16(acc3[3], pa0[cur], pb1[cur] + 2);
            mma_f16(acc3[4], pa1[cur], pb0[cur]); mma_f16(acc3[5], pa1[cur], pb0[cur] + 2);
            mma_f16(acc3[6], pa1[cur], pb1[cur]); mma_f16(acc3[7], pa1[cur], pb1[cur] + 2);
        }

        // ---- store to global ----
        {
            float* gO = out + (size_t)t * (NN * DD);
            const int cb = 2 * fc;
            #pragma unroll
            for (int mb = 0; mb < 2; ++mb) {
                const int j = j0 + 16 * mb + fr;
                #pragma unroll
                for (int nb = 0; nb < 4; ++nb) {
                    const float* a = acc3[mb * 4 + nb];
                    const int col = d0 + 8 * nb + cb;
                    *(float2*)(gO + (size_t)j * DD + col)       = make_float2(a[0], a[1]);
                    *(float2*)(gO + (size_t)(j + 8) * DD + col) = make_float2(a[2], a[3]);
                }
            }
        }
    }
}

extern "C" void kernel_launch(void* const* d_in, const int* in_sizes, int n_in,
                              void* d_out, int out_size)
{
    const float *X = nullptr, *A = nullptr, *W1 = nullptr, *b1 = nullptr,
                *W2 = nullptr, *b2 = nullptr;
    for (int idx = 0; idx < n_in; ++idx) {
        const float* p = (const float*)d_in[idx];
        int s = in_sizes[idx];
        if      (s == NB * NN * NN * DD) X = p;
        else if (s == NB * NN * NN)      A = p;
        else if (s == DD * DD)           { if (!W1) W1 = p; else W2 = p; }
        else if (s == DD)                { if (!b1) b1 = p; else b2 = p; }
    }

    prep_At<<<dim3(4, 4, 32), 256>>>(A);

    cudaFuncSetAttribute(crosssubg_mma_kernel,
                         cudaFuncAttributeMaxDynamicSharedMemorySize, SMEM_BYTES);
    crosssubg_mma_kernel<<<NCTA, 256, SMEM_BYTES>>>(X, W1, b1, W2, b2, (float*)d_out);
}

// round 14
// speedup vs baseline: 1.1944x; 1.0447x over previous
#include <cuda_runtime.h>
#include <cuda_fp16.h>
#include <cstdint>

typedef uint32_t u32;

static constexpr int NB = 32, NN = 128, DD = 64;
static constexpr int NCTA = 296;           // 148 SMs x 2 resident CTAs -> single wave
static constexpr int NTILES = NB * NN;     // 4096

// Precomputed A-transpose fp16 image: At[j][k] = A[b][k][j],
// 128 rows, row stride 136 fp16 (272B), 128 valid k + pad.
__device__ __align__(16) unsigned char g_Ah[32][34816];

// ---------------- helpers ----------------
__device__ __forceinline__ u32 smem_u32(const void* p) {
    u32 a;
    asm("{ .reg .u64 t; cvta.to.shared.u64 t, %1; cvt.u32.u64 %0, t; }" : "=r"(a) : "l"(p));
    return a;
}
__device__ __forceinline__ u32 pack_h16(float lo, float hi) {
    u32 r;
    asm("cvt.rn.f16x2.f32 %0, %1, %2;" : "=r"(r) : "f"(hi), "f"(lo));
    return r;
}
__device__ __forceinline__ void sts32(u32 a, u32 v) {
    asm volatile("st.shared.b32 [%0], %1;" :: "r"(a), "r"(v) : "memory");
}
__device__ __forceinline__ void sts64(u32 a, u32 x, u32 y) {
    asm volatile("st.shared.v2.b32 [%0], {%1,%2};" :: "r"(a), "r"(x), "r"(y) : "memory");
}
__device__ __forceinline__ void sts128(u32 a, u32 x, u32 y, u32 z, u32 w) {
    asm volatile("st.shared.v4.b32 [%0], {%1,%2,%3,%4};" :: "r"(a), "r"(x), "r"(y), "r"(z), "r"(w) : "memory");
}
__device__ __forceinline__ void lds64f(float& x, float& y, u32 a) {
    asm volatile("ld.shared.v2.f32 {%0,%1}, [%2];" : "=f"(x), "=f"(y) : "r"(a));
}
__device__ __forceinline__ void ldsm4(u32* f, u32 a) {
    asm volatile("ldmatrix.sync.aligned.m8n8.x4.shared.b16 {%0,%1,%2,%3}, [%4];"
                 : "=r"(f[0]), "=r"(f[1]), "=r"(f[2]), "=r"(f[3]) : "r"(a));
}
__device__ __forceinline__ void ldsm4t(u32* f, u32 a) {
    asm volatile("ldmatrix.sync.aligned.m8n8.x4.trans.shared.b16 {%0,%1,%2,%3}, [%4];"
                 : "=r"(f[0]), "=r"(f[1]), "=r"(f[2]), "=r"(f[3]) : "r"(a));
}
__device__ __forceinline__ void mma_f16(float* c, const u32* a, const u32* b) {
    asm volatile(
        "mma.sync.aligned.m16n8k16.row.col.f32.f16.f16.f32 "
        "{%0,%1,%2,%3}, {%4,%5,%6,%7}, {%8,%9}, {%0,%1,%2,%3};"
        : "+f"(c[0]), "+f"(c[1]), "+f"(c[2]), "+f"(c[3])
        : "r"(a[0]), "r"(a[1]), "r"(a[2]), "r"(a[3]), "r"(b[0]), "r"(b[1]));
}

#define CP_ASYNC_16(saddr, gptr) \
    asm volatile("cp.async.cg.shared.global [%0], [%1], 16;" \
                 :: "r"(saddr), "l"(gptr) : "memory")
#define CP_ASYNC_COMMIT() asm volatile("cp.async.commit_group;" ::: "memory")
#define CP_ASYNC_WAIT0()  asm volatile("cp.async.wait_group 0;" ::: "memory")

// ---------------- smem layout ----------------
static constexpr u32 RSX   = 288;   // X fp32 row stride (72 floats; 288 % 128 == 32 -> 2-phase lds.64)
static constexpr u32 RS64  = 144;   // 64-wide fp16 tile row stride (bytes)
static constexpr u32 RS128 = 272;   // 128-wide tile row stride

static constexpr u32 OFF_X  = 0;        // 36864 (fp32 X, cp.async target)
static constexpr u32 OFF_W1 = 36864;    // 9216
static constexpr u32 OFF_W2 = 46080;    // 9216
static constexpr u32 OFF_AT = 55296;    // 34816
static constexpr u32 OFF_H2 = 90112;    // 18432
static constexpr u32 OFF_B1 = 108544;   // 256
static constexpr u32 OFF_B2 = 108800;   // 256
static constexpr u32 SMEM_BYTES = 109056; // 2 x 109056 <= 227KB -> 2 CTAs/SM

// =============== prep: A[b][k][j] -> At fp16 image ===============
__global__ void prep_At(const float* __restrict__ A)
{
    __shared__ float tile[32][33];
    const int b = blockIdx.z, k0 = blockIdx.x * 32, j0 = blockIdx.y * 32;
    const int tx = threadIdx.x & 31, ty = threadIdx.x >> 5;   // ty: 0..7

    const float* Ab = A + ((size_t)b * NN + k0) * NN + j0;
    #pragma unroll
    for (int s = 0; s < 4; ++s)
        tile[ty + 8 * s][tx] = Ab[(ty + 8 * s) * NN + tx];
    __syncthreads();

    const int j  = threadIdx.x >> 3;   // 0..31
    const int kq = threadIdx.x & 7;    // 4 k values each
    float v[4];
    #pragma unroll
    for (int s = 0; s < 4; ++s) v[s] = tile[kq * 4 + s][j];

    uint2 h = make_uint2(pack_h16(v[0], v[1]), pack_h16(v[2], v[3]));
    size_t off = (size_t)(j0 + j) * RS128 + (size_t)(k0 + kq * 4) * 2;
    *reinterpret_cast<uint2*>(&g_Ah[b][off]) = h;
}

// async-stage one X tile (fp32) into smem: 8 x LDGSTS.128 per thread
__device__ __forceinline__ void stage_X_async(const float* __restrict__ X, int t,
                                              u32 dst, int tid)
{
    const float* gX = X + (size_t)t * (NN * DD);
    #pragma unroll
    for (int it = 0; it < 8; ++it) {
        int q = tid + it * 256;          // 0..2047 chunks of 16B
        int row = q >> 4, c16 = q & 15;
        CP_ASYNC_16(dst + (u32)row * RSX + (u32)c16 * 16, gX + row * 64 + c16 * 4);
    }
    CP_ASYNC_COMMIT();
}

// =============== main fused persistent kernel ===============
__global__ __launch_bounds__(256, 2)
void crosssubg_mma_kernel(const float* __restrict__ X,
                          const float* __restrict__ W1,
                          const float* __restrict__ b1,
                          const float* __restrict__ W2,
                          const float* __restrict__ b2,
                          float* __restrict__ out)
{
    extern __shared__ __align__(256) unsigned char smraw[];
    const u32 sb = smem_u32(smraw);

    const int cta  = blockIdx.x;
    const int tid  = (int)threadIdx.x;
    const int wid  = tid >> 5;
    const int lane = tid & 31;
    const int row0 = wid * 16;              // G1/G2 m-rows
    const int wm   = wid >> 1, wn = wid & 1;
    const int j0   = wm * 32, d0 = wn * 32; // G3 warp tile origin
    const int fr   = lane >> 2, fc = lane & 3;

    const int t_begin = (int)(((long long)cta * NTILES) / NCTA);
    const int t_end   = (int)(((long long)(cta + 1) * NTILES) / NCTA);

    // ---- one-time staging: W1, W2, biases ----
    {
        const float4* gW1 = (const float4*)W1;   // 1024 each
        const float4* gW2 = (const float4*)W2;
        #pragma unroll
        for (int it = 0; it < 8; ++it) {
            int t = tid + it * 256;              // 0..2047
            int sel = t >> 10;
            int r = t & 1023;
            float4 v = sel ? gW2[r] : gW1[r];
            int d = r >> 4, e0 = (r & 15) * 4;
            sts64(sb + (sel ? OFF_W2 : OFF_W1) + (u32)d * RS64 + (u32)e0 * 2,
                  pack_h16(v.x, v.y), pack_h16(v.z, v.w));
        }
        if (tid < 64)       sts32(sb + OFF_B1 + (u32)tid * 4, __float_as_uint(__ldg(&b1[tid])));
        else if (tid < 128) sts32(sb + OFF_B2 + (u32)(tid - 64) * 4, __float_as_uint(__ldg(&b2[tid - 64])));
    }

    // precomputed addresses
    const u32 xfb   = sb + OFF_X + (u32)(row0 + fr) * RSX + (u32)fc * 8;  // fp32 frag base
    const u32 boffW = (u32)(lane & 15) * RS64 + (u32)(lane >> 4) * 16;
    const u32 aoffA = sb + OFF_AT + ((u32)j0 + (u32)(lane & 15)) * RS128 + (u32)(lane >> 4) * 16;
    const u32 boffH = sb + OFF_H2 + (u32)(lane & 15) * RS64 + (u32)d0 * 2 + (u32)(lane >> 4) * 16;

    int cur_b = -1;

    // prologue: async-stage first X tile
    stage_X_async(X, t_begin, sb + OFF_X, tid);

    for (int t = t_begin; t < t_end; ++t) {
        const int b = t >> 7;   // tile / 128

        // ---- At (re)stage on batch change: <=2 per CTA ----
        if (b != cur_b) {
            __syncthreads();       // no warp still reading At in G3(t-1)
            cur_b = b;
            const uint4* gA = (const uint4*)&g_Ah[b][0];   // 2176 uint4
            #pragma unroll
            for (int it = 0; it < 9; ++it) {
                int q = tid + it * 256;
                if (q < 2176) {
                    uint4 v = gA[q];
                    sts128(sb + OFF_AT + (u32)q * 16, v.x, v.y, v.z, v.w);
                }
            }
        }

        CP_ASYNC_WAIT0();  // X(t) landed (this thread's copies)
        __syncthreads();   // bar1: X (+At) visible to all; all warps past G3(t-1)

        // ---- GEMM1: acc1 = X W1  (A-frags from fp32 smem via lds.64 + cvt) ----
        float acc1[8][4];
        #pragma unroll
        for (int n = 0; n < 8; ++n)
            #pragma unroll
            for (int q = 0; q < 4; ++q) acc1[n][q] = 0.0f;
        #pragma unroll
        for (int ks = 0; ks < 4; ++ks) {
            const u32 xa = xfb + (u32)ks * 64;
            const u32 bb = sb + OFF_W1 + (u32)ks * 16 * RS64 + boffW;
            float x0, x1, x2, x3, x4, x5, x6, x7;
            u32 fb0[4], fb1[4], fb2[4], fb3[4];
            lds64f(x0, x1, xa);
            lds64f(x2, x3, xa + 8u * RSX);
            lds64f(x4, x5, xa + 32);
            lds64f(x6, x7, xa + 8u * RSX + 32);
            ldsm4t(fb0, bb);
            ldsm4t(fb1, bb + 32);
            ldsm4t(fb2, bb + 64);
            ldsm4t(fb3, bb + 96);
            u32 fa[4];
            fa[0] = pack_h16(x0, x1);
            fa[1] = pack_h16(x2, x3);
            fa[2] = pack_h16(x4, x5);
            fa[3] = pack_h16(x6, x7);
            mma_f16(acc1[0], fa, fb0); mma_f16(acc1[1], fa, fb0 + 2);
            mma_f16(acc1[2], fa, fb1); mma_f16(acc1[3], fa, fb1 + 2);
            mma_f16(acc1[4], fa, fb2); mma_f16(acc1[5], fa, fb2 + 2);
            mma_f16(acc1[6], fa, fb3); mma_f16(acc1[7], fa, fb3 + 2);
        }

        // ---- GEMM2: acc2 = relu(acc1 + b1) W2 (A-frags in regs; batched B loads) ----
        float acc2[8][4];
        #pragma unroll
        for (int n = 0; n < 8; ++n)
            #pragma unroll
            for (int q = 0; q < 4; ++q) acc2[n][q] = 0.0f;
        #pragma unroll
        for (int ks = 0; ks < 4; ++ks) {
            const u32 bb = sb + OFF_W2 + (u32)ks * 16 * RS64 + boffW;
            u32 fb0[4], fb1[4], fb2[4], fb3[4];
            ldsm4t(fb0, bb);
            ldsm4t(fb1, bb + 32);
            ldsm4t(fb2, bb + 64);
            ldsm4t(fb3, bb + 96);
            float bz0, bz1, bz2, bz3;
            lds64f(bz0, bz1, sb + OFF_B1 + (u32)(16 * ks + 2 * fc) * 4);
            lds64f(bz2, bz3, sb + OFF_B1 + (u32)(16 * ks + 8 + 2 * fc) * 4);
            u32 fa[4];
            fa[0] = pack_h16(fmaxf(acc1[2 * ks][0] + bz0, 0.f), fmaxf(acc1[2 * ks][1] + bz1, 0.f));
            fa[1] = pack_h16(fmaxf(acc1[2 * ks][2] + bz0, 0.f), fmaxf(acc1[2 * ks][3] + bz1, 0.f));
            fa[2] = pack_h16(fmaxf(acc1[2 * ks + 1][0] + bz2, 0.f), fmaxf(acc1[2 * ks + 1][1] + bz3, 0.f));
            fa[3] = pack_h16(fmaxf(acc1[2 * ks + 1][2] + bz2, 0.f), fmaxf(acc1[2 * ks + 1][3] + bz3, 0.f));
            mma_f16(acc2[0], fa, fb0); mma_f16(acc2[1], fa, fb0 + 2);
            mma_f16(acc2[2], fa, fb1); mma_f16(acc2[3], fa, fb1 + 2);
            mma_f16(acc2[4], fa, fb2); mma_f16(acc2[5], fa, fb2 + 2);
            mma_f16(acc2[6], fa, fb3); mma_f16(acc2[7], fa, fb3 + 2);
        }

        // ---- h2 = relu(acc2 + b2) -> smem fp16 (separate region) ----
        {
            const int r  = row0 + fr;
            const int cb = 2 * fc;
            #pragma unroll
            for (int n0 = 0; n0 < 8; ++n0) {
                const int col = n0 * 8 + cb;
                float bz0, bz1;
                lds64f(bz0, bz1, sb + OFF_B2 + (u32)col * 4);
                float v0 = fmaxf(acc2[n0][0] + bz0, 0.f);
                float v1 = fmaxf(acc2[n0][1] + bz1, 0.f);
                float v2 = fmaxf(acc2[n0][2] + bz0, 0.f);
                float v3 = fmaxf(acc2[n0][3] + bz1, 0.f);
                const u32 a0 = sb + OFF_H2 + (u32)r * RS64 + (u32)col * 2;
                sts32(a0,             pack_h16(v0, v1));
                sts32(a0 + 8u * RS64, pack_h16(v2, v3));
            }
        }
        __syncthreads();   // bar2: h2 visible; all warps past G1(t) -> X buffer free

        // ---- async prefetch X(t+1): issues fast, completes under G3 ----
        if (t + 1 < t_end)
            stage_X_async(X, t + 1, sb + OFF_X, tid);

        // ---- GEMM3 (software-pipelined fragment loads) ----
        float acc3[8][4];
        #pragma unroll
        for (int n = 0; n < 8; ++n)
            #pragma unroll
            for (int q = 0; q < 4; ++q) acc3[n][q] = 0.0f;

        u32 pa0[2][4], pa1[2][4], pb0[2][4], pb1[2][4];
        ldsm4 (pa0[0], aoffA);
        ldsm4 (pa1[0], aoffA + 16u * RS128);
        ldsm4t(pb0[0], boffH);
        ldsm4t(pb1[0], boffH + 32);
        #pragma unroll
        for (int ks = 0; ks < 8; ++ks) {
            const int cur = ks & 1, nxt = cur ^ 1;
            if (ks < 7) {
                const u32 an = aoffA + (u32)(ks + 1) * 32;
                const u32 bn = boffH + (u32)(ks + 1) * 16 * RS64;
                ldsm4 (pa0[nxt], an);
                ldsm4 (pa1[nxt], an + 16u * RS128);
                ldsm4t(pb0[nxt], bn);
                ldsm4t(pb1[nxt], bn + 32);
            }
            mma_f16(acc3[0], pa0[cur], pb0[cur]); mma_f16(acc3[1], pa0[cur], pb0[cur] + 2);
            mma_f16(acc3[2], pa0[cur], pb1[cur]); mma_f16(acc3[3], pa0[cur], pb1[cur] + 2);
            mma_f16(acc3[4], pa1[cur], pb0[cur]); mma_f16(acc3[5], pa1[cur], pb0[cur] + 2);
            mma_f16(acc3[6], pa1[cur], pb1[cur]); mma_f16(acc3[7], pa1[cur], pb1[cur] + 2);
        }

        // ---- store to global ----
        {
            float* gO = out + (size_t)t * (NN * DD);
            const int cb = 2 * fc;
            #pragma unroll
            for (int mb = 0; mb < 2; ++mb) {
                const int j = j0 + 16 * mb + fr;
                #pragma unroll
                for (int nb = 0; nb < 4; ++nb) {
                    const float* a = acc3[mb * 4 + nb];
                    const int col = d0 + 8 * nb + cb;
                    *(float2*)(gO + (size_t)j * DD + col)       = make_float2(a[0], a[1]);
                    *(float2*)(gO + (size_t)(j + 8) * DD + col) = make_float2(a[2], a[3]);
                }
            }
        }
    }
}

extern "C" void kernel_launch(void* const* d_in, const int* in_sizes, int n_in,
                              void* d_out, int out_size)
{
    const float *X = nullptr, *A = nullptr, *W1 = nullptr, *b1 = nullptr,
                *W2 = nullptr, *b2 = nullptr;
    for (int idx = 0; idx < n_in; ++idx) {
        const float* p = (const float*)d_in[idx];
        int s = in_sizes[idx];
        if      (s == NB * NN * NN * DD) X = p;
        else if (s == NB * NN * NN)      A = p;
        else if (s == DD * DD)           { if (!W1) W1 = p; else W2 = p; }
        else if (s == DD)                { if (!b1) b1 = p; else b2 = p; }
    }

    prep_At<<<dim3(4, 4, 32), 256>>>(A);

    cudaFuncSetAttribute(crosssubg_mma_kernel,
                         cudaFuncAttributeMaxDynamicSharedMemorySize, SMEM_BYTES);
    crosssubg_mma_kernel<<<NCTA, 256, SMEM_BYTES>>>(X, W1, b1, W2, b2, (float*)d_out);
}

// round 15
// speedup vs baseline: 1.2303x; 1.0300x over previous
#include <cuda_runtime.h>
#include <cuda_fp16.h>
#include <cstdint>

typedef uint32_t u32;

static constexpr int NB = 32, NN = 128, DD = 64;
static constexpr int NCTA = 296;           // 148 SMs x 2 resident CTAs -> single wave
static constexpr int NTILES = NB * NN;     // 4096

// Precomputed A-transpose fp16 image: At[j][k] = A[b][k][j],
// 128 rows, row stride 136 fp16 (272B), 128 valid k + pad.
__device__ __align__(16) unsigned char g_Ah[32][34816];

// ---------------- helpers ----------------
__device__ __forceinline__ u32 smem_u32(const void* p) {
    u32 a;
    asm("{ .reg .u64 t; cvta.to.shared.u64 t, %1; cvt.u32.u64 %0, t; }" : "=r"(a) : "l"(p));
    return a;
}
__device__ __forceinline__ u32 pack_h16(float lo, float hi) {
    u32 r;
    asm("cvt.rn.f16x2.f32 %0, %1, %2;" : "=r"(r) : "f"(hi), "f"(lo));
    return r;
}
__device__ __forceinline__ void sts32(u32 a, u32 v) {
    asm volatile("st.shared.b32 [%0], %1;" :: "r"(a), "r"(v) : "memory");
}
__device__ __forceinline__ void sts64(u32 a, u32 x, u32 y) {
    asm volatile("st.shared.v2.b32 [%0], {%1,%2};" :: "r"(a), "r"(x), "r"(y) : "memory");
}
__device__ __forceinline__ void sts128(u32 a, u32 x, u32 y, u32 z, u32 w) {
    asm volatile("st.shared.v4.b32 [%0], {%1,%2,%3,%4};" :: "r"(a), "r"(x), "r"(y), "r"(z), "r"(w) : "memory");
}
__device__ __forceinline__ void lds64f(float& x, float& y, u32 a) {
    asm volatile("ld.shared.v2.f32 {%0,%1}, [%2];" : "=f"(x), "=f"(y) : "r"(a));
}
__device__ __forceinline__ void ldsm4(u32* f, u32 a) {
    asm volatile("ldmatrix.sync.aligned.m8n8.x4.shared.b16 {%0,%1,%2,%3}, [%4];"
                 : "=r"(f[0]), "=r"(f[1]), "=r"(f[2]), "=r"(f[3]) : "r"(a));
}
__device__ __forceinline__ void ldsm4t(u32* f, u32 a) {
    asm volatile("ldmatrix.sync.aligned.m8n8.x4.trans.shared.b16 {%0,%1,%2,%3}, [%4];"
                 : "=r"(f[0]), "=r"(f[1]), "=r"(f[2]), "=r"(f[3]) : "r"(a));
}
__device__ __forceinline__ void mma_f16(float* c, const u32* a, const u32* b) {
    asm volatile(
        "mma.sync.aligned.m16n8k16.row.col.f32.f16.f16.f32 "
        "{%0,%1,%2,%3}, {%4,%5,%6,%7}, {%8,%9}, {%0,%1,%2,%3};"
        : "+f"(c[0]), "+f"(c[1]), "+f"(c[2]), "+f"(c[3])
        : "r"(a[0]), "r"(a[1]), "r"(a[2]), "r"(a[3]), "r"(b[0]), "r"(b[1]));
}

#define CP_ASYNC_16(saddr, gptr) \
    asm volatile("cp.async.cg.shared.global [%0], [%1], 16;" \
                 :: "r"(saddr), "l"(gptr) : "memory")
#define CP_ASYNC_COMMIT() asm volatile("cp.async.commit_group;" ::: "memory")
#define CP_ASYNC_WAIT0()  asm volatile("cp.async.wait_group 0;" ::: "memory")

// ---------------- smem layout ----------------
static constexpr u32 RSX   = 288;   // X fp32 row stride
static constexpr u32 RS64  = 144;   // 64-wide fp16 tile row stride (bytes)
static constexpr u32 RS128 = 272;   // 128-wide tile row stride

static constexpr u32 OFF_X  = 0;        // 36864 (fp32 X, cp.async target)
static constexpr u32 OFF_W1 = 36864;    // 9216
static constexpr u32 OFF_W2 = 46080;    // 9216
static constexpr u32 OFF_AT = 55296;    // 34816
static constexpr u32 OFF_H2 = 90112;    // 18432
static constexpr u32 OFF_B1 = 108544;   // 256
static constexpr u32 OFF_B2 = 108800;   // 256
static constexpr u32 SMEM_BYTES = 109056; // 2 CTAs/SM

// =============== prep: A[b][k][j] -> At fp16 image ===============
__global__ void prep_At(const float* __restrict__ A)
{
    __shared__ float tile[32][33];
    const int b = blockIdx.z, k0 = blockIdx.x * 32, j0 = blockIdx.y * 32;
    const int tx = threadIdx.x & 31, ty = threadIdx.x >> 5;   // ty: 0..7

    const float* Ab = A + ((size_t)b * NN + k0) * NN + j0;
    #pragma unroll
    for (int s = 0; s < 4; ++s)
        tile[ty + 8 * s][tx] = Ab[(ty + 8 * s) * NN + tx];
    __syncthreads();

    const int j  = threadIdx.x >> 3;   // 0..31
    const int kq = threadIdx.x & 7;    // 4 k values each
    float v[4];
    #pragma unroll
    for (int s = 0; s < 4; ++s) v[s] = tile[kq * 4 + s][j];

    uint2 h = make_uint2(pack_h16(v[0], v[1]), pack_h16(v[2], v[3]));
    size_t off = (size_t)(j0 + j) * RS128 + (size_t)(k0 + kq * 4) * 2;
    *reinterpret_cast<uint2*>(&g_Ah[b][off]) = h;
}

// async-stage one X tile (fp32) into smem: 8 x LDGSTS.128 per thread
__device__ __forceinline__ void stage_X_async(const float* __restrict__ X, int t,
                                              u32 dst, int tid)
{
    const float* gX = X + (size_t)t * (NN * DD);
    #pragma unroll
    for (int it = 0; it < 8; ++it) {
        int q = tid + it * 256;          // 0..2047 chunks of 16B
        int row = q >> 4, c16 = q & 15;
        CP_ASYNC_16(dst + (u32)row * RSX + (u32)c16 * 16, gX + row * 64 + c16 * 4);
    }
    CP_ASYNC_COMMIT();
}

// =============== main fused persistent kernel ===============
__global__ __launch_bounds__(256, 2)
void crosssubg_mma_kernel(const float* __restrict__ X,
                          const float* __restrict__ W1,
                          const float* __restrict__ b1,
                          const float* __restrict__ W2,
                          const float* __restrict__ b2,
                          float* __restrict__ out)
{
    extern __shared__ __align__(256) unsigned char smraw[];
    const u32 sb = smem_u32(smraw);

    const int cta  = blockIdx.x;
    const int tid  = (int)threadIdx.x;
    const int wid  = tid >> 5;
    const int lane = tid & 31;
    const int row0 = wid * 16;              // G1/G2 m-rows
    const int wm   = wid >> 1, wn = wid & 1;
    const int j0   = wm * 32, d0 = wn * 32; // G3 warp tile origin
    const int fr   = lane >> 2, fc = lane & 3;

    const int t_begin = (int)(((long long)cta * NTILES) / NCTA);
    const int t_end   = (int)(((long long)(cta + 1) * NTILES) / NCTA);

    // ---- one-time staging: W1, W2, biases ----
    {
        const float4* gW1 = (const float4*)W1;   // 1024 each
        const float4* gW2 = (const float4*)W2;
        #pragma unroll
        for (int it = 0; it < 8; ++it) {
            int t = tid + it * 256;              // 0..2047
            int sel = t >> 10;
            int r = t & 1023;
            float4 v = sel ? gW2[r] : gW1[r];
            int d = r >> 4, e0 = (r & 15) * 4;
            sts64(sb + (sel ? OFF_W2 : OFF_W1) + (u32)d * RS64 + (u32)e0 * 2,
                  pack_h16(v.x, v.y), pack_h16(v.z, v.w));
        }
        if (tid < 64)       sts32(sb + OFF_B1 + (u32)tid * 4, __float_as_uint(__ldg(&b1[tid])));
        else if (tid < 128) sts32(sb + OFF_B2 + (u32)(tid - 64) * 4, __float_as_uint(__ldg(&b2[tid - 64])));
    }
    __syncthreads();   // biases visible for register hoist

    // ---- hoist loop-invariant biases into registers ----
    float rb1[4][4];   // G2 fragment bias: [ks][bz0..bz3]
    float rb2[8][2];   // h2 epilogue bias: [n0][2]
    #pragma unroll
    for (int ks = 0; ks < 4; ++ks) {
        lds64f(rb1[ks][0], rb1[ks][1], sb + OFF_B1 + (u32)(16 * ks + 2 * fc) * 4);
        lds64f(rb1[ks][2], rb1[ks][3], sb + OFF_B1 + (u32)(16 * ks + 8 + 2 * fc) * 4);
    }
    #pragma unroll
    for (int n0 = 0; n0 < 8; ++n0)
        lds64f(rb2[n0][0], rb2[n0][1], sb + OFF_B2 + (u32)(n0 * 8 + 2 * fc) * 4);

    // precomputed addresses
    const u32 xfb   = sb + OFF_X + (u32)(row0 + fr) * RSX + (u32)fc * 8;  // fp32 frag base
    const u32 boffW = (u32)(lane & 15) * RS64 + (u32)(lane >> 4) * 16;
    const u32 aoffA = sb + OFF_AT + ((u32)j0 + (u32)(lane & 15)) * RS128 + (u32)(lane >> 4) * 16;
    const u32 boffH = sb + OFF_H2 + (u32)(lane & 15) * RS64 + (u32)d0 * 2 + (u32)(lane >> 4) * 16;

    int cur_b = -1;

    // prologue: async-stage first X tile
    stage_X_async(X, t_begin, sb + OFF_X, tid);

    for (int t = t_begin; t < t_end; ++t) {
        const int b = t >> 7;   // tile / 128

        // ---- At (re)stage on batch change: <=2 per CTA ----
        if (b != cur_b) {
            __syncthreads();       // no warp still reading At in G3(t-1)
            cur_b = b;
            const uint4* gA = (const uint4*)&g_Ah[b][0];   // 2176 uint4
            #pragma unroll
            for (int it = 0; it < 9; ++it) {
                int q = tid + it * 256;
                if (q < 2176) {
                    uint4 v = gA[q];
                    sts128(sb + OFF_AT + (u32)q * 16, v.x, v.y, v.z, v.w);
                }
            }
        }

        CP_ASYNC_WAIT0();  // X(t) landed (this thread's copies)
        __syncthreads();   // bar1: X (+At) visible to all; all warps past G3(t-1)

        // ---- GEMM1: acc1 = X W1  (A-frags from fp32 smem via lds.64 + cvt) ----
        float acc1[8][4];
        #pragma unroll
        for (int n = 0; n < 8; ++n)
            #pragma unroll
            for (int q = 0; q < 4; ++q) acc1[n][q] = 0.0f;
        #pragma unroll
        for (int ks = 0; ks < 4; ++ks) {
            const u32 xa = xfb + (u32)ks * 64;
            const u32 bb = sb + OFF_W1 + (u32)ks * 16 * RS64 + boffW;
            float x0, x1, x2, x3, x4, x5, x6, x7;
            u32 fb0[4], fb1[4], fb2[4], fb3[4];
            lds64f(x0, x1, xa);
            lds64f(x2, x3, xa + 8u * RSX);
            lds64f(x4, x5, xa + 32);
            lds64f(x6, x7, xa + 8u * RSX + 32);
            ldsm4t(fb0, bb);
            ldsm4t(fb1, bb + 32);
            ldsm4t(fb2, bb + 64);
            ldsm4t(fb3, bb + 96);
            u32 fa[4];
            fa[0] = pack_h16(x0, x1);
            fa[1] = pack_h16(x2, x3);
            fa[2] = pack_h16(x4, x5);
            fa[3] = pack_h16(x6, x7);
            mma_f16(acc1[0], fa, fb0); mma_f16(acc1[1], fa, fb0 + 2);
            mma_f16(acc1[2], fa, fb1); mma_f16(acc1[3], fa, fb1 + 2);
            mma_f16(acc1[4], fa, fb2); mma_f16(acc1[5], fa, fb2 + 2);
            mma_f16(acc1[6], fa, fb3); mma_f16(acc1[7], fa, fb3 + 2);
        }

        // ---- GEMM2: acc2 = relu(acc1 + b1) W2 (A-frags in regs; bias from regs) ----
        float acc2[8][4];
        #pragma unroll
        for (int n = 0; n < 8; ++n)
            #pragma unroll
            for (int q = 0; q < 4; ++q) acc2[n][q] = 0.0f;
        #pragma unroll
        for (int ks = 0; ks < 4; ++ks) {
            const u32 bb = sb + OFF_W2 + (u32)ks * 16 * RS64 + boffW;
            u32 fb0[4], fb1[4], fb2[4], fb3[4];
            ldsm4t(fb0, bb);
            ldsm4t(fb1, bb + 32);
            ldsm4t(fb2, bb + 64);
            ldsm4t(fb3, bb + 96);
            u32 fa[4];
            fa[0] = pack_h16(fmaxf(acc1[2 * ks][0] + rb1[ks][0], 0.f),
                             fmaxf(acc1[2 * ks][1] + rb1[ks][1], 0.f));
            fa[1] = pack_h16(fmaxf(acc1[2 * ks][2] + rb1[ks][0], 0.f),
                             fmaxf(acc1[2 * ks][3] + rb1[ks][1], 0.f));
            fa[2] = pack_h16(fmaxf(acc1[2 * ks + 1][0] + rb1[ks][2], 0.f),
                             fmaxf(acc1[2 * ks + 1][1] + rb1[ks][3], 0.f));
            fa[3] = pack_h16(fmaxf(acc1[2 * ks + 1][2] + rb1[ks][2], 0.f),
                             fmaxf(acc1[2 * ks + 1][3] + rb1[ks][3], 0.f));
            mma_f16(acc2[0], fa, fb0); mma_f16(acc2[1], fa, fb0 + 2);
            mma_f16(acc2[2], fa, fb1); mma_f16(acc2[3], fa, fb1 + 2);
            mma_f16(acc2[4], fa, fb2); mma_f16(acc2[5], fa, fb2 + 2);
            mma_f16(acc2[6], fa, fb3); mma_f16(acc2[7], fa, fb3 + 2);
        }

        // ---- h2 = relu(acc2 + b2) -> smem fp16 (bias from regs) ----
        {
            const int r = row0 + fr;
            #pragma unroll
            for (int n0 = 0; n0 < 8; ++n0) {
                const int col = n0 * 8 + 2 * fc;
                float v0 = fmaxf(acc2[n0][0] + rb2[n0][0], 0.f);
                float v1 = fmaxf(acc2[n0][1] + rb2[n0][1], 0.f);
                float v2 = fmaxf(acc2[n0][2] + rb2[n0][0], 0.f);
                float v3 = fmaxf(acc2[n0][3] + rb2[n0][1], 0.f);
                const u32 a0 = sb + OFF_H2 + (u32)r * RS64 + (u32)col * 2;
                sts32(a0,             pack_h16(v0, v1));
                sts32(a0 + 8u * RS64, pack_h16(v2, v3));
            }
        }
        __syncthreads();   // bar2: h2 visible; all warps past G1(t) -> X buffer free

        // ---- async prefetch X(t+1): completes under G3 ----
        if (t + 1 < t_end)
            stage_X_async(X, t + 1, sb + OFF_X, tid);

        // ---- GEMM3: out[j][d] = sum_k At[j][k] h2[k][d]  (batched per-ks loads) ----
        float acc3[8][4];
        #pragma unroll
        for (int n = 0; n < 8; ++n)
            #pragma unroll
            for (int q = 0; q < 4; ++q) acc3[n][q] = 0.0f;
        #pragma unroll
        for (int ks = 0; ks < 8; ++ks) {
            u32 fa0[4], fa1[4], fb0[4], fb1[4];
            const u32 an = aoffA + (u32)ks * 32;
            const u32 bn = boffH + (u32)ks * 16 * RS64;
            ldsm4 (fa0, an);
            ldsm4 (fa1, an + 16u * RS128);
            ldsm4t(fb0, bn);
            ldsm4t(fb1, bn + 32);
            mma_f16(acc3[0], fa0, fb0); mma_f16(acc3[1], fa0, fb0 + 2);
            mma_f16(acc3[2], fa0, fb1); mma_f16(acc3[3], fa0, fb1 + 2);
            mma_f16(acc3[4], fa1, fb0); mma_f16(acc3[5], fa1, fb0 + 2);
            mma_f16(acc3[6], fa1, fb1); mma_f16(acc3[7], fa1, fb1 + 2);
        }

        // ---- store to global ----
        {
            float* gO = out + (size_t)t * (NN * DD);
            const int cb = 2 * fc;
            #pragma unroll
            for (int mb = 0; mb < 2; ++mb) {
                const int j = j0 + 16 * mb + fr;
                #pragma unroll
                for (int nb = 0; nb < 4; ++nb) {
                    const float* a = acc3[mb * 4 + nb];
                    const int col = d0 + 8 * nb + cb;
                    *(float2*)(gO + (size_t)j * DD + col)       = make_float2(a[0], a[1]);
                    *(float2*)(gO + (size_t)(j + 8) * DD + col) = make_float2(a[2], a[3]);
                }
            }
        }
    }
}

extern "C" void kernel_launch(void* const* d_in, const int* in_sizes, int n_in,
                              void* d_out, int out_size)
{
    const float *X = nullptr, *A = nullptr, *W1 = nullptr, *b1 = nullptr,
                *W2 = nullptr, *b2 = nullptr;
    for (int idx = 0; idx < n_in; ++idx) {
        const float* p = (const float*)d_in[idx];
        int s = in_sizes[idx];
        if      (s == NB * NN * NN * DD) X = p;
        else if (s == NB * NN * NN)      A = p;
        else if (s == DD * DD)           { if (!W1) W1 = p; else W2 = p; }
        else if (s == DD)                { if (!b1) b1 = p; else b2 = p; }
    }

    prep_At<<<dim3(4, 4, 32), 256>>>(A);

    cudaFuncSetAttribute(crosssubg_mma_kernel,
                         cudaFuncAttributeMaxDynamicSharedMemorySize, SMEM_BYTES);
    crosssubg_mma_kernel<<<NCTA, 256, SMEM_BYTES>>>(X, W1, b1, W2, b2, (float*)d_out);
}

// round 16
// speedup vs baseline: 1.2626x; 1.0263x over previous
#include <cuda_runtime.h>
#include <cuda_fp16.h>
#include <cstdint>

typedef uint32_t u32;

static constexpr int NB = 32, NN = 128, DD = 64;
static constexpr int NCTA = 148;           // 1 CTA per SM, single wave
static constexpr int NTILES = NB * NN;     // 4096

// Precomputed A-transpose fp16 image: At[j][k] = A[b][k][j],
// 128 rows, row stride 136 fp16 (272B), 128 valid k + pad.
__device__ __align__(16) unsigned char g_Ah[32][34816];

// ---------------- helpers ----------------
__device__ __forceinline__ u32 smem_u32(const void* p) {
    u32 a;
    asm("{ .reg .u64 t; cvta.to.shared.u64 t, %1; cvt.u32.u64 %0, t; }" : "=r"(a) : "l"(p));
    return a;
}
__device__ __forceinline__ u32 pack_h16(float lo, float hi) {
    u32 r;
    asm("cvt.rn.f16x2.f32 %0, %1, %2;" : "=r"(r) : "f"(hi), "f"(lo));
    return r;
}
__device__ __forceinline__ void sts32(u32 a, u32 v) {
    asm volatile("st.shared.b32 [%0], %1;" :: "r"(a), "r"(v) : "memory");
}
__device__ __forceinline__ void sts64(u32 a, u32 x, u32 y) {
    asm volatile("st.shared.v2.b32 [%0], {%1,%2};" :: "r"(a), "r"(x), "r"(y) : "memory");
}
__device__ __forceinline__ void sts128(u32 a, u32 x, u32 y, u32 z, u32 w) {
    asm volatile("st.shared.v4.b32 [%0], {%1,%2,%3,%4};" :: "r"(a), "r"(x), "r"(y), "r"(z), "r"(w) : "memory");
}
__device__ __forceinline__ void lds64f(float& x, float& y, u32 a) {
    asm volatile("ld.shared.v2.f32 {%0,%1}, [%2];" : "=f"(x), "=f"(y) : "r"(a));
}
__device__ __forceinline__ void ldsm4(u32* f, u32 a) {
    asm volatile("ldmatrix.sync.aligned.m8n8.x4.shared.b16 {%0,%1,%2,%3}, [%4];"
                 : "=r"(f[0]), "=r"(f[1]), "=r"(f[2]), "=r"(f[3]) : "r"(a));
}
__device__ __forceinline__ void ldsm4t(u32* f, u32 a) {
    asm volatile("ldmatrix.sync.aligned.m8n8.x4.trans.shared.b16 {%0,%1,%2,%3}, [%4];"
                 : "=r"(f[0]), "=r"(f[1]), "=r"(f[2]), "=r"(f[3]) : "r"(a));
}
__device__ __forceinline__ void mma_f16(float* c, const u32* a, const u32* b) {
    asm volatile(
        "mma.sync.aligned.m16n8k16.row.col.f32.f16.f16.f32 "
        "{%0,%1,%2,%3}, {%4,%5,%6,%7}, {%8,%9}, {%0,%1,%2,%3};"
        : "+f"(c[0]), "+f"(c[1]), "+f"(c[2]), "+f"(c[3])
        : "r"(a[0]), "r"(a[1]), "r"(a[2]), "r"(a[3]), "r"(b[0]), "r"(b[1]));
}

#define CP_ASYNC_16(saddr, gptr) \
    asm volatile("cp.async.cg.shared.global [%0], [%1], 16;" \
                 :: "r"(saddr), "l"(gptr) : "memory")
#define CP_ASYNC_COMMIT() asm volatile("cp.async.commit_group;" ::: "memory")
#define CP_ASYNC_WAIT0()  asm volatile("cp.async.wait_group 0;" ::: "memory")

// ---------------- smem layout ----------------
static constexpr u32 RSX   = 288;   // X fp32 row stride
static constexpr u32 RS64  = 144;   // 64-wide fp16 tile row stride (bytes)
static constexpr u32 RS128 = 272;   // 128-wide tile row stride

static constexpr u32 OFF_X  = 0;        // 36864 (fp32 X, cp.async target)
static constexpr u32 OFF_W1 = 36864;    // 9216 (used once to preload fragments)
static constexpr u32 OFF_W2 = 46080;    // 9216
static constexpr u32 OFF_AT = 55296;    // 34816
static constexpr u32 OFF_H2 = 90112;    // 18432
static constexpr u32 OFF_B1 = 108544;   // 256
static constexpr u32 OFF_B2 = 108800;   // 256
static constexpr u32 SMEM_BYTES = 109056; // 1 CTA/SM

// =============== prep: A[b][k][j] -> At fp16 image ===============
__global__ void prep_At(const float* __restrict__ A)
{
    __shared__ float tile[32][33];
    const int b = blockIdx.z, k0 = blockIdx.x * 32, j0 = blockIdx.y * 32;
    const int tx = threadIdx.x & 31, ty = threadIdx.x >> 5;   // ty: 0..7

    const float* Ab = A + ((size_t)b * NN + k0) * NN + j0;
    #pragma unroll
    for (int s = 0; s < 4; ++s)
        tile[ty + 8 * s][tx] = Ab[(ty + 8 * s) * NN + tx];
    __syncthreads();

    const int j  = threadIdx.x >> 3;   // 0..31
    const int kq = threadIdx.x & 7;    // 4 k values each
    float v[4];
    #pragma unroll
    for (int s = 0; s < 4; ++s) v[s] = tile[kq * 4 + s][j];

    uint2 h = make_uint2(pack_h16(v[0], v[1]), pack_h16(v[2], v[3]));
    size_t off = (size_t)(j0 + j) * RS128 + (size_t)(k0 + kq * 4) * 2;
    *reinterpret_cast<uint2*>(&g_Ah[b][off]) = h;
}

// async-stage one X tile (fp32) into smem: 8 x LDGSTS.128 per thread
__device__ __forceinline__ void stage_X_async(const float* __restrict__ X, int t,
                                              u32 dst, int tid)
{
    const float* gX = X + (size_t)t * (NN * DD);
    #pragma unroll
    for (int it = 0; it < 8; ++it) {
        int q = tid + it * 256;          // 0..2047 chunks of 16B
        int row = q >> 4, c16 = q & 15;
        CP_ASYNC_16(dst + (u32)row * RSX + (u32)c16 * 16, gX + row * 64 + c16 * 4);
    }
    CP_ASYNC_COMMIT();
}

// =============== main fused persistent kernel ===============
__global__ __launch_bounds__(256, 1)
void crosssubg_mma_kernel(const float* __restrict__ X,
                          const float* __restrict__ W1,
                          const float* __restrict__ b1,
                          const float* __restrict__ W2,
                          const float* __restrict__ b2,
                          float* __restrict__ out)
{
    extern __shared__ __align__(256) unsigned char smraw[];
    const u32 sb = smem_u32(smraw);

    const int cta  = blockIdx.x;
    const int tid  = (int)threadIdx.x;
    const int wid  = tid >> 5;
    const int lane = tid & 31;
    const int row0 = wid * 16;              // G1/G2 m-rows
    const int wm   = wid >> 1, wn = wid & 1;
    const int j0   = wm * 32, d0 = wn * 32; // G3 warp tile origin
    const int fr   = lane >> 2, fc = lane & 3;

    const int t_begin = (int)(((long long)cta * NTILES) / NCTA);
    const int t_end   = (int)(((long long)(cta + 1) * NTILES) / NCTA);

    // ---- one-time staging: W1, W2, biases into smem ----
    {
        const float4* gW1 = (const float4*)W1;   // 1024 each
        const float4* gW2 = (const float4*)W2;
        #pragma unroll
        for (int it = 0; it < 8; ++it) {
            int t = tid + it * 256;              // 0..2047
            int sel = t >> 10;
            int r = t & 1023;
            float4 v = sel ? gW2[r] : gW1[r];
            int d = r >> 4, e0 = (r & 15) * 4;
            sts64(sb + (sel ? OFF_W2 : OFF_W1) + (u32)d * RS64 + (u32)e0 * 2,
                  pack_h16(v.x, v.y), pack_h16(v.z, v.w));
        }
        if (tid < 64)       sts32(sb + OFF_B1 + (u32)tid * 4, __float_as_uint(__ldg(&b1[tid])));
        else if (tid < 128) sts32(sb + OFF_B2 + (u32)(tid - 64) * 4, __float_as_uint(__ldg(&b2[tid - 64])));
    }
    __syncthreads();

    // ---- preload W1/W2 B-fragments into registers (held for the whole kernel) ----
    const u32 boffW = (u32)(lane & 15) * RS64 + (u32)(lane >> 4) * 16;
    u32 w1f[4][4][4], w2f[4][4][4];   // [ks][np][reg]
    #pragma unroll
    for (int ks = 0; ks < 4; ++ks) {
        const u32 b1a = sb + OFF_W1 + (u32)ks * 16 * RS64 + boffW;
        const u32 b2a = sb + OFF_W2 + (u32)ks * 16 * RS64 + boffW;
        #pragma unroll
        for (int np = 0; np < 4; ++np) {
            ldsm4t(w1f[ks][np], b1a + (u32)np * 32);
            ldsm4t(w2f[ks][np], b2a + (u32)np * 32);
        }
    }

    // precomputed addresses
    const u32 xfb   = sb + OFF_X + (u32)(row0 + fr) * RSX + (u32)fc * 8;  // fp32 frag base
    const u32 aoffA = sb + OFF_AT + ((u32)j0 + (u32)(lane & 15)) * RS128 + (u32)(lane >> 4) * 16;
    const u32 boffH = sb + OFF_H2 + (u32)(lane & 15) * RS64 + (u32)d0 * 2 + (u32)(lane >> 4) * 16;

    int cur_b = -1;

    // prologue: async-stage first X tile
    stage_X_async(X, t_begin, sb + OFF_X, tid);

    for (int t = t_begin; t < t_end; ++t) {
        const int b = t >> 7;   // tile / 128

        // ---- At (re)stage on batch change ----
        if (b != cur_b) {
            __syncthreads();       // no warp still reading At in G3(t-1)
            cur_b = b;
            const uint4* gA = (const uint4*)&g_Ah[b][0];   // 2176 uint4
            #pragma unroll
            for (int it = 0; it < 9; ++it) {
                int q = tid + it * 256;
                if (q < 2176) {
                    uint4 v = gA[q];
                    sts128(sb + OFF_AT + (u32)q * 16, v.x, v.y, v.z, v.w);
                }
            }
        }

        CP_ASYNC_WAIT0();  // X(t) landed (this thread's copies)
        __syncthreads();   // bar1: X (+At) visible; all warps past G3(t-1)

        // ---- GEMM1: acc1 = X W1  (A-frags from fp32 smem; W1 from registers) ----
        float acc1[8][4];
        #pragma unroll
        for (int n = 0; n < 8; ++n)
            #pragma unroll
            for (int q = 0; q < 4; ++q) acc1[n][q] = 0.0f;
        #pragma unroll
        for (int ks = 0; ks < 4; ++ks) {
            const u32 xa = xfb + (u32)ks * 64;
            float x0, x1, x2, x3, x4, x5, x6, x7;
            lds64f(x0, x1, xa);
            lds64f(x2, x3, xa + 8u * RSX);
            lds64f(x4, x5, xa + 32);
            lds64f(x6, x7, xa + 8u * RSX + 32);
            u32 fa[4];
            fa[0] = pack_h16(x0, x1);
            fa[1] = pack_h16(x2, x3);
            fa[2] = pack_h16(x4, x5);
            fa[3] = pack_h16(x6, x7);
            #pragma unroll
            for (int np = 0; np < 4; ++np) {
                mma_f16(acc1[2 * np],     fa, w1f[ks][np]);
                mma_f16(acc1[2 * np + 1], fa, w1f[ks][np] + 2);
            }
        }

        // ---- early-convert: h1 fragments = relu(acc1 + b1) -> 16 regs; acc1 dies ----
        u32 h1f[4][4];
        #pragma unroll
        for (int ks = 0; ks < 4; ++ks) {
            float bz0, bz1, bz2, bz3;
            lds64f(bz0, bz1, sb + OFF_B1 + (u32)(16 * ks + 2 * fc) * 4);
            lds64f(bz2, bz3, sb + OFF_B1 + (u32)(16 * ks + 8 + 2 * fc) * 4);
            h1f[ks][0] = pack_h16(fmaxf(acc1[2 * ks][0] + bz0, 0.f),
                                  fmaxf(acc1[2 * ks][1] + bz1, 0.f));
            h1f[ks][1] = pack_h16(fmaxf(acc1[2 * ks][2] + bz0, 0.f),
                                  fmaxf(acc1[2 * ks][3] + bz1, 0.f));
            h1f[ks][2] = pack_h16(fmaxf(acc1[2 * ks + 1][0] + bz2, 0.f),
                                  fmaxf(acc1[2 * ks + 1][1] + bz3, 0.f));
            h1f[ks][3] = pack_h16(fmaxf(acc1[2 * ks + 1][2] + bz2, 0.f),
                                  fmaxf(acc1[2 * ks + 1][3] + bz3, 0.f));
        }

        // ---- GEMM2: acc2 = h1 W2 (both operands in registers) ----
        float acc2[8][4];
        #pragma unroll
        for (int n = 0; n < 8; ++n)
            #pragma unroll
            for (int q = 0; q < 4; ++q) acc2[n][q] = 0.0f;
        #pragma unroll
        for (int ks = 0; ks < 4; ++ks) {
            #pragma unroll
            for (int np = 0; np < 4; ++np) {
                mma_f16(acc2[2 * np],     h1f[ks], w2f[ks][np]);
                mma_f16(acc2[2 * np + 1], h1f[ks], w2f[ks][np] + 2);
            }
        }

        // ---- h2 = relu(acc2 + b2) -> smem fp16 ----
        {
            const int r = row0 + fr;
            #pragma unroll
            for (int n0 = 0; n0 < 8; ++n0) {
                const int col = n0 * 8 + 2 * fc;
                float bz0, bz1;
                lds64f(bz0, bz1, sb + OFF_B2 + (u32)(n0 * 8 + 2 * fc) * 4);
                float v0 = fmaxf(acc2[n0][0] + bz0, 0.f);
                float v1 = fmaxf(acc2[n0][1] + bz1, 0.f);
                float v2 = fmaxf(acc2[n0][2] + bz0, 0.f);
                float v3 = fmaxf(acc2[n0][3] + bz1, 0.f);
                const u32 a0 = sb + OFF_H2 + (u32)r * RS64 + (u32)col * 2;
                sts32(a0,             pack_h16(v0, v1));
                sts32(a0 + 8u * RS64, pack_h16(v2, v3));
            }
        }
        __syncthreads();   // bar2: h2 visible; all warps past G1(t) -> X buffer free

        // ---- async prefetch X(t+1): completes under G3 ----
        if (t + 1 < t_end)
            stage_X_async(X, t + 1, sb + OFF_X, tid);

        // ---- GEMM3: out[j][d] = sum_k At[j][k] h2[k][d]  (warp tile 32x32) ----
        float acc3[8][4];
        #pragma unroll
        for (int n = 0; n < 8; ++n)
            #pragma unroll
            for (int q = 0; q < 4; ++q) acc3[n][q] = 0.0f;
        #pragma unroll
        for (int ks = 0; ks < 8; ++ks) {
            u32 fa0[4], fa1[4], fb0[4], fb1[4];
            const u32 an = aoffA + (u32)ks * 32;
            const u32 bn = boffH + (u32)ks * 16 * RS64;
            ldsm4 (fa0, an);
            ldsm4 (fa1, an + 16u * RS128);
            ldsm4t(fb0, bn);
            ldsm4t(fb1, bn + 32);
            mma_f16(acc3[0], fa0, fb0); mma_f16(acc3[1], fa0, fb0 + 2);
            mma_f16(acc3[2], fa0, fb1); mma_f16(acc3[3], fa0, fb1 + 2);
            mma_f16(acc3[4], fa1, fb0); mma_f16(acc3[5], fa1, fb0 + 2);
            mma_f16(acc3[6], fa1, fb1); mma_f16(acc3[7], fa1, fb1 + 2);
        }

        // ---- store to global ----
        {
            float* gO = out + (size_t)t * (NN * DD);
            const int cb = 2 * fc;
            #pragma unroll
            for (int mb = 0; mb < 2; ++mb) {
                const int j = j0 + 16 * mb + fr;
                #pragma unroll
                for (int nb = 0; nb < 4; ++nb) {
                    const float* a = acc3[mb * 4 + nb];
                    const int col = d0 + 8 * nb + cb;
                    *(float2*)(gO + (size_t)j * DD + col)       = make_float2(a[0], a[1]);
                    *(float2*)(gO + (size_t)(j + 8) * DD + col) = make_float2(a[2], a[3]);
                }
            }
        }
    }
}

extern "C" void kernel_launch(void* const* d_in, const int* in_sizes, int n_in,
                              void* d_out, int out_size)
{
    const float *X = nullptr, *A = nullptr, *W1 = nullptr, *b1 = nullptr,
                *W2 = nullptr, *b2 = nullptr;
    for (int idx = 0; idx < n_in; ++idx) {
        const float* p = (const float*)d_in[idx];
        int s = in_sizes[idx];
        if      (s == NB * NN * NN * DD) X = p;
        else if (s == NB * NN * NN)      A = p;
        else if (s == DD * DD)           { if (!W1) W1 = p; else W2 = p; }
        else if (s == DD)                { if (!b1) b1 = p; else b2 = p; }
    }

    prep_At<<<dim3(4, 4, 32), 256>>>(A);

    cudaFuncSetAttribute(crosssubg_mma_kernel,
                         cudaFuncAttributeMaxDynamicSharedMemorySize, SMEM_BYTES);
    crosssubg_mma_kernel<<<NCTA, 256, SMEM_BYTES>>>(X, W1, b1, W2, b2, (float*)d_out);
}

// round 17
// speedup vs baseline: 1.3333x; 1.0560x over previous
#include <cuda_runtime.h>
#include <cuda_fp16.h>
#include <cstdint>

typedef uint32_t u32;

static constexpr int NB = 32, NN = 128, DD = 64;
static constexpr int NCTA = 148;           // 1 CTA per SM, single wave
static constexpr int NTILES = NB * NN;     // 4096

// Precomputed A-transpose fp16 image: At[j][k] = A[b][k][j],
// 128 rows, row stride 136 fp16 (272B).
__device__ __align__(16) unsigned char g_Ah[32][34816];

// ---------------- helpers ----------------
__device__ __forceinline__ u32 smem_u32(const void* p) {
    u32 a;
    asm("{ .reg .u64 t; cvta.to.shared.u64 t, %1; cvt.u32.u64 %0, t; }" : "=r"(a) : "l"(p));
    return a;
}
__device__ __forceinline__ u32 pack_h16(float lo, float hi) {
    u32 r;
    asm("cvt.rn.f16x2.f32 %0, %1, %2;" : "=r"(r) : "f"(hi), "f"(lo));
    return r;
}
__device__ __forceinline__ void sts32(u32 a, u32 v) {
    asm volatile("st.shared.b32 [%0], %1;" :: "r"(a), "r"(v) : "memory");
}
__device__ __forceinline__ void sts64(u32 a, u32 x, u32 y) {
    asm volatile("st.shared.v2.b32 [%0], {%1,%2};" :: "r"(a), "r"(x), "r"(y) : "memory");
}
__device__ __forceinline__ void sts128(u32 a, u32 x, u32 y, u32 z, u32 w) {
    asm volatile("st.shared.v4.b32 [%0], {%1,%2,%3,%4};" :: "r"(a), "r"(x), "r"(y), "r"(z), "r"(w) : "memory");
}
__device__ __forceinline__ void lds64f(float& x, float& y, u32 a) {
    asm volatile("ld.shared.v2.f32 {%0,%1}, [%2];" : "=f"(x), "=f"(y) : "r"(a));
}
__device__ __forceinline__ void ldsm4(u32* f, u32 a) {
    asm volatile("ldmatrix.sync.aligned.m8n8.x4.shared.b16 {%0,%1,%2,%3}, [%4];"
                 : "=r"(f[0]), "=r"(f[1]), "=r"(f[2]), "=r"(f[3]) : "r"(a));
}
__device__ __forceinline__ void ldsm4t(u32* f, u32 a) {
    asm volatile("ldmatrix.sync.aligned.m8n8.x4.trans.shared.b16 {%0,%1,%2,%3}, [%4];"
                 : "=r"(f[0]), "=r"(f[1]), "=r"(f[2]), "=r"(f[3]) : "r"(a));
}
__device__ __forceinline__ void mma_f16(float* c, const u32* a, const u32* b) {
    asm volatile(
        "mma.sync.aligned.m16n8k16.row.col.f32.f16.f16.f32 "
        "{%0,%1,%2,%3}, {%4,%5,%6,%7}, {%8,%9}, {%0,%1,%2,%3};"
        : "+f"(c[0]), "+f"(c[1]), "+f"(c[2]), "+f"(c[3])
        : "r"(a[0]), "r"(a[1]), "r"(a[2]), "r"(a[3]), "r"(b[0]), "r"(b[1]));
}

#define CP_ASYNC_16(saddr, gptr) \
    asm volatile("cp.async.cg.shared.global [%0], [%1], 16;" \
                 :: "r"(saddr), "l"(gptr) : "memory")
#define CP_ASYNC_COMMIT() asm volatile("cp.async.commit_group;" ::: "memory")
#define CP_ASYNC_WAIT0()  asm volatile("cp.async.wait_group 0;" ::: "memory")

#define BAR_SYNC(id, cnt)   asm volatile("bar.sync %0, %1;"   :: "r"(id), "r"(cnt) : "memory")
#define BAR_ARRIVE(id, cnt) asm volatile("bar.arrive %0, %1;" :: "r"(id), "r"(cnt) : "memory")
// barrier ids: 1,2 = full[p]; 3,4 = empty[p]; 5 = MLP-internal; 6 = AGG-internal

// ---------------- smem layout ----------------
static constexpr u32 RSX   = 288;   // X fp32 row stride
static constexpr u32 RS64  = 144;   // 64-wide fp16 tile row stride (bytes)
static constexpr u32 RS128 = 272;   // 128-wide tile row stride

static constexpr u32 OFF_X0  = 0;        // 36864 (fp32 X, cp.async target)
static constexpr u32 OFF_X1  = 36864;    // 36864
static constexpr u32 OFF_W1  = 73728;    // 9216
static constexpr u32 OFF_W2  = 82944;    // 9216
static constexpr u32 OFF_AT  = 92160;    // 34816
static constexpr u32 OFF_H2A = 126976;   // 18432
static constexpr u32 OFF_H2B = 145408;   // 18432
static constexpr u32 OFF_B1  = 163840;   // 256
static constexpr u32 OFF_B2  = 164096;   // 256
static constexpr u32 SMEM_BYTES = 164352; // 1 CTA/SM

// =============== prep: A[b][k][j] -> At fp16 image ===============
__global__ void prep_At(const float* __restrict__ A)
{
    __shared__ float tile[32][33];
    const int b = blockIdx.z, k0 = blockIdx.x * 32, j0 = blockIdx.y * 32;
    const int tx = threadIdx.x & 31, ty = threadIdx.x >> 5;

    const float* Ab = A + ((size_t)b * NN + k0) * NN + j0;
    #pragma unroll
    for (int s = 0; s < 4; ++s)
        tile[ty + 8 * s][tx] = Ab[(ty + 8 * s) * NN + tx];
    __syncthreads();

    const int j  = threadIdx.x >> 3;
    const int kq = threadIdx.x & 7;
    float v[4];
    #pragma unroll
    for (int s = 0; s < 4; ++s) v[s] = tile[kq * 4 + s][j];

    uint2 h = make_uint2(pack_h16(v[0], v[1]), pack_h16(v[2], v[3]));
    size_t off = (size_t)(j0 + j) * RS128 + (size_t)(k0 + kq * 4) * 2;
    *reinterpret_cast<uint2*>(&g_Ah[b][off]) = h;
}

// async-stage one X tile (fp32) by the 128 MLP threads (16 LDGSTS.128 each)
__device__ __forceinline__ void stage_X_async(const float* __restrict__ X, int t,
                                              u32 dst, int tid128)
{
    const float* gX = X + (size_t)t * (NN * DD);
    #pragma unroll
    for (int it = 0; it < 16; ++it) {
        int q = tid128 + it * 128;       // 0..2047 chunks of 16B
        int row = q >> 4, c16 = q & 15;
        CP_ASYNC_16(dst + (u32)row * RSX + (u32)c16 * 16, gX + row * 64 + c16 * 4);
    }
    CP_ASYNC_COMMIT();
}

// =============== main fused warp-specialized persistent kernel ===============
__global__ __launch_bounds__(256, 1)
void crosssubg_mma_kernel(const float* __restrict__ X,
                          const float* __restrict__ W1,
                          const float* __restrict__ b1,
                          const float* __restrict__ W2,
                          const float* __restrict__ b2,
                          float* __restrict__ out)
{
    extern __shared__ __align__(256) unsigned char smraw[];
    const u32 sb = smem_u32(smraw);

    const int tid  = (int)threadIdx.x;
    const int wid  = tid >> 5;
    const int lane = tid & 31;
    const int fr   = lane >> 2, fc = lane & 3;

    const int cta = blockIdx.x;
    const int t_begin = (int)(((long long)cta * NTILES) / NCTA);
    const int t_end   = (int)(((long long)(cta + 1) * NTILES) / NCTA);

    // ---- one-time staging: W1, W2, biases (all 256 threads) ----
    {
        const float4* gW1 = (const float4*)W1;
        const float4* gW2 = (const float4*)W2;
        #pragma unroll
        for (int it = 0; it < 8; ++it) {
            int t = tid + it * 256;              // 0..2047
            int sel = t >> 10;
            int r = t & 1023;
            float4 v = sel ? gW2[r] : gW1[r];
            int d = r >> 4, e0 = (r & 15) * 4;
            sts64(sb + (sel ? OFF_W2 : OFF_W1) + (u32)d * RS64 + (u32)e0 * 2,
                  pack_h16(v.x, v.y), pack_h16(v.z, v.w));
        }
        if (tid < 64)       sts32(sb + OFF_B1 + (u32)tid * 4, __float_as_uint(__ldg(&b1[tid])));
        else if (tid < 128) sts32(sb + OFF_B2 + (u32)(tid - 64) * 4, __float_as_uint(__ldg(&b2[tid - 64])));
    }
    __syncthreads();

    if (wid < 4) {
        // ================= MLP group: G1 + G2, produce h2 =================
        const int tid128 = tid;              // 0..127
        const u32 boffW = (u32)(lane & 15) * RS64 + (u32)(lane >> 4) * 16;

        // preload W1/W2 B-fragments (held in registers for the whole kernel)
        u32 w1f[4][4][4], w2f[4][4][4];      // [ks][np][reg]
        #pragma unroll
        for (int ks = 0; ks < 4; ++ks) {
            const u32 b1a = sb + OFF_W1 + (u32)ks * 16 * RS64 + boffW;
            const u32 b2a = sb + OFF_W2 + (u32)ks * 16 * RS64 + boffW;
            #pragma unroll
            for (int np = 0; np < 4; ++np) {
                ldsm4t(w1f[ks][np], b1a + (u32)np * 32);
                ldsm4t(w2f[ks][np], b2a + (u32)np * 32);
            }
        }

        // prologue: async-stage first X tile
        stage_X_async(X, t_begin, sb + ((t_begin & 1) ? OFF_X1 : OFF_X0), tid128);

        for (int t = t_begin; t < t_end; ++t) {
            const u32 xbuf  = sb + ((t & 1) ? OFF_X1 : OFF_X0);
            const u32 h2buf = sb + ((t & 1) ? OFF_H2B : OFF_H2A);

            CP_ASYNC_WAIT0();                // X(t) landed (this thread's copies)
            if (t - t_begin >= 2) BAR_SYNC(3 + (t & 1), 256);  // empty[p]: AGG done with h2(t-2); also X-visibility
            else                  BAR_SYNC(5, 128);            // X-visibility only

            // prefetch X(t+1) into the other buffer (free since the barrier above)
            if (t + 1 < t_end)
                stage_X_async(X, t + 1, sb + (((t + 1) & 1) ? OFF_X1 : OFF_X0), tid128);

            #pragma unroll
            for (int mb = 0; mb < 2; ++mb) {
                const int row0m = wid * 32 + mb * 16;
                const u32 xfb = xbuf + (u32)(row0m + fr) * RSX + (u32)fc * 8;

                // ---- G1: acc1 = X W1 (W1 in regs) ----
                float acc1[8][4];
                #pragma unroll
                for (int n = 0; n < 8; ++n)
                    #pragma unroll
                    for (int q = 0; q < 4; ++q) acc1[n][q] = 0.0f;
                #pragma unroll
                for (int ks = 0; ks < 4; ++ks) {
                    const u32 xa = xfb + (u32)ks * 64;
                    float x0, x1, x2, x3, x4, x5, x6, x7;
                    lds64f(x0, x1, xa);
                    lds64f(x2, x3, xa + 8u * RSX);
                    lds64f(x4, x5, xa + 32);
                    lds64f(x6, x7, xa + 8u * RSX + 32);
                    u32 fa[4];
                    fa[0] = pack_h16(x0, x1);
                    fa[1] = pack_h16(x2, x3);
                    fa[2] = pack_h16(x4, x5);
                    fa[3] = pack_h16(x6, x7);
                    #pragma unroll
                    for (int np = 0; np < 4; ++np) {
                        mma_f16(acc1[2 * np],     fa, w1f[ks][np]);
                        mma_f16(acc1[2 * np + 1], fa, w1f[ks][np] + 2);
                    }
                }

                // ---- early-convert h1 fragments (acc1 dies) ----
                u32 h1f[4][4];
                #pragma unroll
                for (int ks = 0; ks < 4; ++ks) {
                    float bz0, bz1, bz2, bz3;
                    lds64f(bz0, bz1, sb + OFF_B1 + (u32)(16 * ks + 2 * fc) * 4);
                    lds64f(bz2, bz3, sb + OFF_B1 + (u32)(16 * ks + 8 + 2 * fc) * 4);
                    h1f[ks][0] = pack_h16(fmaxf(acc1[2 * ks][0] + bz0, 0.f),
                                          fmaxf(acc1[2 * ks][1] + bz1, 0.f));
                    h1f[ks][1] = pack_h16(fmaxf(acc1[2 * ks][2] + bz0, 0.f),
                                          fmaxf(acc1[2 * ks][3] + bz1, 0.f));
                    h1f[ks][2] = pack_h16(fmaxf(acc1[2 * ks + 1][0] + bz2, 0.f),
                                          fmaxf(acc1[2 * ks + 1][1] + bz3, 0.f));
                    h1f[ks][3] = pack_h16(fmaxf(acc1[2 * ks + 1][2] + bz2, 0.f),
                                          fmaxf(acc1[2 * ks + 1][3] + bz3, 0.f));
                }

                // ---- G2: acc2 = h1 W2 (all-register) ----
                float acc2[8][4];
                #pragma unroll
                for (int n = 0; n < 8; ++n)
                    #pragma unroll
                    for (int q = 0; q < 4; ++q) acc2[n][q] = 0.0f;
                #pragma unroll
                for (int ks = 0; ks < 4; ++ks) {
                    #pragma unroll
                    for (int np = 0; np < 4; ++np) {
                        mma_f16(acc2[2 * np],     h1f[ks], w2f[ks][np]);
                        mma_f16(acc2[2 * np + 1], h1f[ks], w2f[ks][np] + 2);
                    }
                }

                // ---- h2 = relu(acc2 + b2) -> h2buf ----
                const int r = row0m + fr;
                #pragma unroll
                for (int n0 = 0; n0 < 8; ++n0) {
                    const int col = n0 * 8 + 2 * fc;
                    float bz0, bz1;
                    lds64f(bz0, bz1, sb + OFF_B2 + (u32)(n0 * 8 + 2 * fc) * 4);
                    float v0 = fmaxf(acc2[n0][0] + bz0, 0.f);
                    float v1 = fmaxf(acc2[n0][1] + bz1, 0.f);
                    float v2 = fmaxf(acc2[n0][2] + bz0, 0.f);
                    float v3 = fmaxf(acc2[n0][3] + bz1, 0.f);
                    const u32 a0 = h2buf + (u32)r * RS64 + (u32)col * 2;
                    sts32(a0,             pack_h16(v0, v1));
                    sts32(a0 + 8u * RS64, pack_h16(v2, v3));
                }
            }

            BAR_ARRIVE(1 + (t & 1), 256);    // full[p]: h2(t) ready
        }
    } else {
        // ================= AGG group: G3, consume h2, write out =================
        const int tida = tid - 128;          // 0..127
        const int wa   = wid - 4;            // 0..3
        const int j0   = wa * 32;
        const u32 aoffA = sb + OFF_AT + ((u32)j0 + (u32)(lane & 15)) * RS128 + (u32)(lane >> 4) * 16;
        const u32 boffH0 = (u32)(lane & 15) * RS64 + (u32)(lane >> 4) * 16;

        int cur_b = -1;

        for (int t = t_begin; t < t_end; ++t) {
            const int b = t >> 7;
            const u32 h2buf = sb + ((t & 1) ? OFF_H2B : OFF_H2A);

            // ---- At (re)stage on batch change (AGG-internal) ----
            if (b != cur_b) {
                BAR_SYNC(6, 128);            // all AGG warps past G3(t-1) At reads
                cur_b = b;
                const uint4* gA = (const uint4*)&g_Ah[b][0];   // 2176 uint4
                #pragma unroll
                for (int it = 0; it < 17; ++it) {
                    int q = tida + it * 128;
                    if (q < 2176) {
                        uint4 v = gA[q];
                        sts128(sb + OFF_AT + (u32)q * 16, v.x, v.y, v.z, v.w);
                    }
                }
                BAR_SYNC(6, 128);            // At visible
            }

            BAR_SYNC(1 + (t & 1), 256);      // full[p]: wait h2(t)

            // ---- G3: out[j][d] = sum_k At[j][k] h2[k][d]  (warp tile 32x64) ----
            float acc3[2][8][4];
            #pragma unroll
            for (int mb = 0; mb < 2; ++mb)
                #pragma unroll
                for (int n = 0; n < 8; ++n)
                    #pragma unroll
                    for (int q = 0; q < 4; ++q) acc3[mb][n][q] = 0.0f;

            #pragma unroll
            for (int ks = 0; ks < 8; ++ks) {
                u32 fa0[4], fa1[4], fb[4][4];
                const u32 an = aoffA + (u32)ks * 32;
                const u32 bn = h2buf + boffH0 + (u32)ks * 16 * RS64;
                ldsm4(fa0, an);
                ldsm4(fa1, an + 16u * RS128);
                #pragma unroll
                for (int np = 0; np < 4; ++np) ldsm4t(fb[np], bn + (u32)np * 32);
                #pragma unroll
                for (int np = 0; np < 4; ++np) {
                    mma_f16(acc3[0][2 * np],     fa0, fb[np]);
                    mma_f16(acc3[0][2 * np + 1], fa0, fb[np] + 2);
                    mma_f16(acc3[1][2 * np],     fa1, fb[np]);
                    mma_f16(acc3[1][2 * np + 1], fa1, fb[np] + 2);
                }
            }

            BAR_ARRIVE(3 + (t & 1), 256);    // empty[p]: h2(t) consumed

            // ---- store to global ----
            float* gO = out + (size_t)t * (NN * DD);
            const int cb = 2 * fc;
            #pragma unroll
            for (int mb = 0; mb < 2; ++mb) {
                const int j = j0 + 16 * mb + fr;
                #pragma unroll
                for (int nb = 0; nb < 8; ++nb) {
                    const float* a = acc3[mb][nb];
                    const int col = nb * 8 + cb;
                    *(float2*)(gO + (size_t)j * DD + col)       = make_float2(a[0], a[1]);
                    *(float2*)(gO + (size_t)(j + 8) * DD + col) = make_float2(a[2], a[3]);
                }
            }
        }
    }

    __syncthreads();   // keep all threads resident until both groups drain
}

extern "C" void kernel_launch(void* const* d_in, const int* in_sizes, int n_in,
                              void* d_out, int out_size)
{
    const float *X = nullptr, *A = nullptr, *W1 = nullptr, *b1 = nullptr,
                *W2 = nullptr, *b2 = nullptr;
    for (int idx = 0; idx < n_in; ++idx) {
        const float* p = (const float*)d_in[idx];
        int s = in_sizes[idx];
        if      (s == NB * NN * NN * DD) X = p;
        else if (s == NB * NN * NN)      A = p;
        else if (s == DD * DD)           { if (!W1) W1 = p; else W2 = p; }
        else if (s == DD)                { if (!b1) b1 = p; else b2 = p; }
    }

    prep_At<<<dim3(4, 4, 32), 256>>>(A);

    cudaFuncSetAttribute(crosssubg_mma_kernel,
                         cudaFuncAttributeMaxDynamicSharedMemorySize, SMEM_BYTES);
    crosssubg_mma_kernel<<<NCTA, 256, SMEM_BYTES>>>(X, W1, b1, W2, b2, (float*)d_out);
}